// round 4
// baseline (speedup 1.0000x reference)
#include <cuda_runtime.h>
#include <math.h>
#include <stdint.h>

#define B 1024
#define L 18
#define E 300
#define H 300
#define G4 1200
#define KP 304      // padded K for recurrence
#define VS 2186
#define BL (B*L)

// ---------------- scratch ----------------
__device__ float g_ag[B * E];
__device__ float g_w [B * E];
__device__ float g_sproj[2][VS * G4];     // interleaved cols n'=4j+gate
__device__ float g_wproj[2][B * G4];      // interleaved
__device__ float g_Vh[BL * 2 * H];
__device__ float g_hhi[2][2][B * KP];     // [dir][pingpong][b*304+k], tf32 hi
__device__ float g_hlo[2][2][B * KP];     // tf32 lo
__device__ float g_c  [2][B * H];
__device__ float g_Whi[2][G4 * KP];       // Whh permuted [n'][k], tf32 hi
__device__ float g_Wlo[2][G4 * KP];

// ---------------- helpers ----------------
__device__ __forceinline__ void sp32(float x, float& hi, float& lo) {
    uint32_t u; asm("cvt.rna.tf32.f32 %0, %1;" : "=r"(u) : "f"(x));
    float h = __uint_as_float(u);
    float r = x - h;
    uint32_t u2; asm("cvt.rna.tf32.f32 %0, %1;" : "=r"(u2) : "f"(r));
    hi = h; lo = __uint_as_float(u2);
}

__device__ __forceinline__ void mma8(float* c,
    uint32_t a0, uint32_t a1, uint32_t a2, uint32_t a3,
    uint32_t b0, uint32_t b1) {
    asm volatile("mma.sync.aligned.m16n8k8.row.col.f32.tf32.tf32.f32 "
        "{%0,%1,%2,%3},{%4,%5,%6,%7},{%8,%9},{%0,%1,%2,%3};"
        : "+f"(c[0]), "+f"(c[1]), "+f"(c[2]), "+f"(c[3])
        : "r"(a0), "r"(a1), "r"(a2), "r"(a3), "r"(b0), "r"(b1));
}

#define FU(x) __float_as_uint(x)

// ---------------- init ----------------
__global__ void zero_state_kernel() {
    int i = blockIdx.x * blockDim.x + threadIdx.x;
    if (i < 2 * 2 * B * KP) { (&g_hhi[0][0][0])[i] = 0.f; (&g_hlo[0][0][0])[i] = 0.f; }
    if (i < 2 * B * H)      (&g_c[0][0])[i] = 0.f;
}

// ---------------- Whh prep: permute to [n'=4j+g][k], pad k, split hi/lo ----------------
__global__ void prep_whh(const float* __restrict__ Wf, const float* __restrict__ Wb) {
    int i = blockIdx.x * blockDim.x + threadIdx.x;
    if (i >= 2 * G4 * KP) return;
    int dir = i / (G4 * KP);
    int r   = i - dir * (G4 * KP);
    int np  = r / KP, k = r - np * KP;
    const float* W = dir ? Wb : Wf;
    float v = (k < H) ? W[(size_t)((np & 3) * H + (np >> 2)) * H + k] : 0.f;
    float hi, lo; sp32(v, hi, lo);
    g_Whi[dir][r] = hi;
    g_Wlo[dir][r] = lo;
}

// ---------------- embedding gather ----------------
__global__ void embed_kernel(const int* __restrict__ word,
                             const int* __restrict__ sem,
                             const float* __restrict__ wt,
                             const float* __restrict__ st) {
    int b = blockIdx.x;
    int e = threadIdx.x;
    __shared__ int sidx[L];
    __shared__ int widx;
    if (e < L) sidx[e] = sem[b * L + e];
    if (e == 0) widx = word[b];
    __syncthreads();
    if (e < E) {
        float acc = 0.f;
#pragma unroll
        for (int l = 0; l < L; l++) acc += st[sidx[l] * E + e];
        g_ag[b * E + e] = acc * (1.f / (float)L);
        g_w [b * E + e] = wt[widx * E + e];
    }
}

// ---------------- generic split-tf32 GEMM ----------------
// C[m][n] = A(MxK,lda) @ Wrow(n)^T + b1 + b2 [relu], Wrow(n) = imap ? (n&3)*H+(n>>2) : n
// Block tile 128x128, 8 warps (2m x 4n), warp tile 64x32. blockIdx.z picks set.
__global__ void __launch_bounds__(256)
mma_gemm(const float* __restrict__ A, int lda,
         const float* __restrict__ W0, const float* __restrict__ W1, int ldw, int imap,
         const float* __restrict__ b10, const float* __restrict__ b11,
         const float* __restrict__ b20, const float* __restrict__ b21,
         float* __restrict__ C0, float* __restrict__ C1,
         int M, int N, int K, int dorelu) {
    int z = blockIdx.z;
    const float* W  = z ? W1 : W0;
    const float* b1 = z ? b11 : b10;
    const float* b2 = z ? b21 : b20;
    float* C        = z ? C1 : C0;

    __shared__ float sm[10240];
    float* Ah = sm;          float* Al = sm + 2560;
    float* Bh = sm + 5120;   float* Bl = sm + 7680;

    int tid = threadIdx.x;
    int lane = tid & 31, wid = tid >> 5;
    int g = lane >> 2, t4 = lane & 3;
    int wm = (wid >> 2) * 64, wn = (wid & 3) * 32;
    int m0 = blockIdx.y * 128, n0 = blockIdx.x * 128;

    float acc[4][4][4];
#pragma unroll
    for (int a = 0; a < 4; a++)
#pragma unroll
        for (int b = 0; b < 4; b++)
#pragma unroll
            for (int c = 0; c < 4; c++) acc[a][b][c] = 0.f;

    int nch = (K + 15) / 16;
    for (int kc = 0; kc < nch; kc++) {
        int k0 = kc * 16;
        bool kfull = (k0 + 16 <= K);
        float4 ra[2], rb[2];
#pragma unroll
        for (int q = 0; q < 2; q++) {
            int e = tid + q * 256;
            int ml = e >> 2, k4 = (e & 3) * 4;
            // A
            int row = m0 + ml;
            float4 v = make_float4(0.f, 0.f, 0.f, 0.f);
            if (row < M) {
                if (kfull) v = *(const float4*)(A + (size_t)row * lda + k0 + k4);
                else {
                    int kk = k0 + k4;
                    if (kk + 0 < K) v.x = A[(size_t)row * lda + kk + 0];
                    if (kk + 1 < K) v.y = A[(size_t)row * lda + kk + 1];
                    if (kk + 2 < K) v.z = A[(size_t)row * lda + kk + 2];
                    if (kk + 3 < K) v.w = A[(size_t)row * lda + kk + 3];
                }
            }
            ra[q] = v;
            // B
            int nr = n0 + ml;
            float4 w = make_float4(0.f, 0.f, 0.f, 0.f);
            if (nr < N) {
                int grow = imap ? ((nr & 3) * H + (nr >> 2)) : nr;
                const float* wp = W + (size_t)grow * ldw;
                if (kfull) w = *(const float4*)(wp + k0 + k4);
                else {
                    int kk = k0 + k4;
                    if (kk + 0 < K) w.x = wp[kk + 0];
                    if (kk + 1 < K) w.y = wp[kk + 1];
                    if (kk + 2 < K) w.z = wp[kk + 2];
                    if (kk + 3 < K) w.w = wp[kk + 3];
                }
            }
            rb[q] = w;
        }
        __syncthreads();
#pragma unroll
        for (int q = 0; q < 2; q++) {
            int e = tid + q * 256;
            int ml = e >> 2, k4 = (e & 3) * 4;
            float4 h4, l4;
            sp32(ra[q].x, h4.x, l4.x); sp32(ra[q].y, h4.y, l4.y);
            sp32(ra[q].z, h4.z, l4.z); sp32(ra[q].w, h4.w, l4.w);
            *(float4*)&Ah[ml * 20 + k4] = h4;
            *(float4*)&Al[ml * 20 + k4] = l4;
            sp32(rb[q].x, h4.x, l4.x); sp32(rb[q].y, h4.y, l4.y);
            sp32(rb[q].z, h4.z, l4.z); sp32(rb[q].w, h4.w, l4.w);
            *(float4*)&Bh[ml * 20 + k4] = h4;
            *(float4*)&Bl[ml * 20 + k4] = l4;
        }
        __syncthreads();
#pragma unroll
        for (int ks = 0; ks < 2; ks++) {
            int kb = ks * 8 + t4;
            uint32_t ah[4][4], al[4][4];
#pragma unroll
            for (int im = 0; im < 4; im++) {
                int r = wm + im * 16 + g;
                ah[im][0] = FU(Ah[r * 20 + kb]);
                ah[im][1] = FU(Ah[(r + 8) * 20 + kb]);
                ah[im][2] = FU(Ah[r * 20 + kb + 4]);
                ah[im][3] = FU(Ah[(r + 8) * 20 + kb + 4]);
                al[im][0] = FU(Al[r * 20 + kb]);
                al[im][1] = FU(Al[(r + 8) * 20 + kb]);
                al[im][2] = FU(Al[r * 20 + kb + 4]);
                al[im][3] = FU(Al[(r + 8) * 20 + kb + 4]);
            }
#pragma unroll
            for (int in8 = 0; in8 < 4; in8++) {
                int cn = wn + in8 * 8 + g;
                uint32_t bh0 = FU(Bh[cn * 20 + kb]);
                uint32_t bh1 = FU(Bh[cn * 20 + kb + 4]);
                uint32_t bl0 = FU(Bl[cn * 20 + kb]);
                uint32_t bl1 = FU(Bl[cn * 20 + kb + 4]);
#pragma unroll
                for (int im = 0; im < 4; im++) {
                    mma8(acc[im][in8], ah[im][0], ah[im][1], ah[im][2], ah[im][3], bh0, bh1);
                    mma8(acc[im][in8], al[im][0], al[im][1], al[im][2], al[im][3], bh0, bh1);
                    mma8(acc[im][in8], ah[im][0], ah[im][1], ah[im][2], ah[im][3], bl0, bl1);
                }
            }
        }
        __syncthreads();
    }

    // epilogue
#pragma unroll
    for (int in8 = 0; in8 < 4; in8++) {
        int n_g = n0 + wn + in8 * 8 + 2 * t4;
        float bv0 = 0.f, bv1 = 0.f;
        if (n_g < N) {
            int i0 = imap ? ((n_g & 3) * H + (n_g >> 2)) : n_g;
            if (b1) bv0 += b1[i0];
            if (b2) bv0 += b2[i0];
        }
        if (n_g + 1 < N) {
            int i1 = imap ? (((n_g + 1) & 3) * H + ((n_g + 1) >> 2)) : (n_g + 1);
            if (b1) bv1 += b1[i1];
            if (b2) bv1 += b2[i1];
        }
#pragma unroll
        for (int im = 0; im < 4; im++) {
            int r0 = m0 + wm + im * 16 + g;
            if (r0 < M) {
                if (n_g < N) {
                    float v = acc[im][in8][0] + bv0;
                    if (dorelu) v = fmaxf(v, 0.f);
                    C[(size_t)r0 * N + n_g] = v;
                }
                if (n_g + 1 < N) {
                    float v = acc[im][in8][1] + bv1;
                    if (dorelu) v = fmaxf(v, 0.f);
                    C[(size_t)r0 * N + n_g + 1] = v;
                }
            }
            int r1 = r0 + 8;
            if (r1 < M) {
                if (n_g < N) {
                    float v = acc[im][in8][2] + bv0;
                    if (dorelu) v = fmaxf(v, 0.f);
                    C[(size_t)r1 * N + n_g] = v;
                }
                if (n_g + 1 < N) {
                    float v = acc[im][in8][3] + bv1;
                    if (dorelu) v = fmaxf(v, 0.f);
                    C[(size_t)r1 * N + n_g + 1] = v;
                }
            }
        }
    }
}

// ---------------- LSTM step via split-tf32 mma ----------------
// preact[b][n'] = h_prev @ Whh'(n')^T (split), then gates from sproj/wproj gather.
// grid (10 n-tiles, 8 m-tiles, 2 dirs), block 256 thr, tile 128x128, K=304.
__global__ void __launch_bounds__(256)
lstm_step_mma(int st, const int* __restrict__ sem) {
    int dir = blockIdx.z;
    const float* Ahg = g_hhi[dir][st & 1];
    const float* Alg = g_hlo[dir][st & 1];
    float* Hh = g_hhi[dir][(st + 1) & 1];
    float* Hl = g_hlo[dir][(st + 1) & 1];
    const float* Whi = g_Whi[dir];
    const float* Wlo = g_Wlo[dir];
    const float* sproj = g_sproj[dir];
    const float* wproj = g_wproj[dir];
    float* cbuf = g_c[dir];
    int t = dir ? (L - 1 - st) : st;

    __shared__ float sm[10240];
    float* Ah = sm;          float* Al = sm + 2560;
    float* Bh = sm + 5120;   float* Bl = sm + 7680;

    int tid = threadIdx.x;
    int lane = tid & 31, wid = tid >> 5;
    int g = lane >> 2, t4 = lane & 3;
    int wmi = wid >> 2;
    int wm = wmi * 64, wn = (wid & 3) * 32;
    int m0 = blockIdx.y * 128, n0 = blockIdx.x * 128;
    int j0 = blockIdx.x * 32;

    float acc[4][4][4];
#pragma unroll
    for (int a = 0; a < 4; a++)
#pragma unroll
        for (int b = 0; b < 4; b++)
#pragma unroll
            for (int c = 0; c < 4; c++) acc[a][b][c] = 0.f;

    for (int kc = 0; kc < KP / 16; kc++) {
        int k0 = kc * 16;
        float4 rah[2], ral[2], rbh[2], rbl[2];
#pragma unroll
        for (int q = 0; q < 2; q++) {
            int e = tid + q * 256;
            int ml = e >> 2, k4 = (e & 3) * 4;
            size_t aoff = (size_t)(m0 + ml) * KP + k0 + k4;
            rah[q] = *(const float4*)(Ahg + aoff);
            ral[q] = *(const float4*)(Alg + aoff);
            int nr = n0 + ml;
            if (nr < G4) {
                size_t boff = (size_t)nr * KP + k0 + k4;
                rbh[q] = *(const float4*)(Whi + boff);
                rbl[q] = *(const float4*)(Wlo + boff);
            } else {
                rbh[q] = make_float4(0.f, 0.f, 0.f, 0.f);
                rbl[q] = rbh[q];
            }
        }
        __syncthreads();
#pragma unroll
        for (int q = 0; q < 2; q++) {
            int e = tid + q * 256;
            int ml = e >> 2, k4 = (e & 3) * 4;
            *(float4*)&Ah[ml * 20 + k4] = rah[q];
            *(float4*)&Al[ml * 20 + k4] = ral[q];
            *(float4*)&Bh[ml * 20 + k4] = rbh[q];
            *(float4*)&Bl[ml * 20 + k4] = rbl[q];
        }
        __syncthreads();
#pragma unroll
        for (int ks = 0; ks < 2; ks++) {
            int kb = ks * 8 + t4;
            uint32_t ah[4][4], al[4][4];
#pragma unroll
            for (int im = 0; im < 4; im++) {
                int r = wm + im * 16 + g;
                ah[im][0] = FU(Ah[r * 20 + kb]);
                ah[im][1] = FU(Ah[(r + 8) * 20 + kb]);
                ah[im][2] = FU(Ah[r * 20 + kb + 4]);
                ah[im][3] = FU(Ah[(r + 8) * 20 + kb + 4]);
                al[im][0] = FU(Al[r * 20 + kb]);
                al[im][1] = FU(Al[(r + 8) * 20 + kb]);
                al[im][2] = FU(Al[r * 20 + kb + 4]);
                al[im][3] = FU(Al[(r + 8) * 20 + kb + 4]);
            }
#pragma unroll
            for (int in8 = 0; in8 < 4; in8++) {
                int cn = wn + in8 * 8 + g;
                uint32_t bh0 = FU(Bh[cn * 20 + kb]);
                uint32_t bh1 = FU(Bh[cn * 20 + kb + 4]);
                uint32_t bl0 = FU(Bl[cn * 20 + kb]);
                uint32_t bl1 = FU(Bl[cn * 20 + kb + 4]);
#pragma unroll
                for (int im = 0; im < 4; im++) {
                    mma8(acc[im][in8], ah[im][0], ah[im][1], ah[im][2], ah[im][3], bh0, bh1);
                    mma8(acc[im][in8], al[im][0], al[im][1], al[im][2], al[im][3], bh0, bh1);
                    mma8(acc[im][in8], ah[im][0], ah[im][1], ah[im][2], ah[im][3], bl0, bl1);
                }
            }
        }
        __syncthreads();
    }

    // epilogue: two halves of 64 batch rows; preacts via smem, scalar gates
    for (int half = 0; half < 2; half++) {
        __syncthreads();
        if (wmi == half) {
#pragma unroll
            for (int in8 = 0; in8 < 4; in8++) {
                int cn = wn + in8 * 8 + 2 * t4;
#pragma unroll
                for (int im = 0; im < 4; im++) {
                    int rl = im * 16 + g;
                    *(float2*)&sm[rl * 132 + cn] =
                        make_float2(acc[im][in8][0], acc[im][in8][1]);
                    *(float2*)&sm[(rl + 8) * 132 + cn] =
                        make_float2(acc[im][in8][2], acc[im][in8][3]);
                }
            }
        }
        __syncthreads();
#pragma unroll
        for (int q = 0; q < 8; q++) {
            int e = tid + q * 256;
            int bl = e >> 5, jl = e & 31;
            int j = j0 + jl;
            if (j < H) {
                int b = m0 + half * 64 + bl;
                int idx = sem[b * L + t];
                float4 cs = *(float4*)&sm[bl * 132 + jl * 4];
                float4 sp = *(const float4*)(sproj + (size_t)idx * G4 + 4 * j);
                float4 wp = *(const float4*)(wproj + (size_t)b * G4 + 4 * j);
                float wmul = (idx != 0) ? 1.f : 0.f;
                float gi = cs.x + sp.x + wmul * wp.x;
                float gf = cs.y + sp.y + wmul * wp.y;
                float gg = cs.z + sp.z + wmul * wp.z;
                float go = cs.w + sp.w + wmul * wp.w;
                float ig = 1.f / (1.f + expf(-gi));
                float fg = 1.f / (1.f + expf(-gf));
                float gt = tanhf(gg);
                float og = 1.f / (1.f + expf(-go));
                float cn = fg * cbuf[b * H + j] + ig * gt;
                cbuf[b * H + j] = cn;
                float h = og * tanhf(cn);
                g_Vh[(size_t)(b * L + t) * (2 * H) + dir * H + j] = h;
                float hh, hl; sp32(h, hh, hl);
                Hh[(size_t)b * KP + j] = hh;
                Hl[(size_t)b * KP + j] = hl;
            }
        }
    }
}

// ---------------- launch ----------------
extern "C" void kernel_launch(void* const* d_in, const int* in_sizes, int n_in,
                              void* d_out, int out_size) {
    const int*   word  = (const int*)d_in[0];
    const int*   sem   = (const int*)d_in[1];
    const float* wt    = (const float*)d_in[2];
    const float* st    = (const float*)d_in[3];
    const float* Wih_f = (const float*)d_in[4];
    const float* Whh_f = (const float*)d_in[5];
    const float* bih_f = (const float*)d_in[6];
    const float* bhh_f = (const float*)d_in[7];
    const float* Wih_b = (const float*)d_in[8];
    const float* Whh_b = (const float*)d_in[9];
    const float* bih_b = (const float*)d_in[10];
    const float* bhh_b = (const float*)d_in[11];
    const float* Wa    = (const float*)d_in[12];
    const float* ba    = (const float*)d_in[13];
    const float* Wb    = (const float*)d_in[14];
    const float* bb    = (const float*)d_in[15];

    float* out    = (float*)d_out;
    float* Vout   = out;                       // (B, L, H)
    float* vg_out = out + (size_t)B * L * H;   // (B, E)

    void* p;
    float *pag, *pw, *psf, *psb, *pwf, *pwb, *pvh;
    cudaGetSymbolAddress(&p, g_ag);    pag = (float*)p;
    cudaGetSymbolAddress(&p, g_w);     pw  = (float*)p;
    cudaGetSymbolAddress(&p, g_sproj); psf = (float*)p; psb = psf + (size_t)VS * G4;
    cudaGetSymbolAddress(&p, g_wproj); pwf = (float*)p; pwb = pwf + (size_t)B * G4;
    cudaGetSymbolAddress(&p, g_Vh);    pvh = (float*)p;

    zero_state_kernel<<<(2 * 2 * B * KP + 255) / 256, 256>>>();
    prep_whh<<<(2 * G4 * KP + 255) / 256, 256>>>(Whh_f, Whh_b);
    embed_kernel<<<B, 320>>>(word, sem, wt, st);

    // v_g = relu(a_g @ Wb^T + bb)
    mma_gemm<<<dim3(3, 8, 1), 256>>>(
        pag, E, Wb, Wb, E, 0, bb, bb, nullptr, nullptr,
        vg_out, vg_out, B, E, E, 1);

    // s_proj (interleaved cols) = sem_table @ Wih[:,E:]^T + bih + bhh
    mma_gemm<<<dim3(10, 18, 2), 256>>>(
        st, E, Wih_f + E, Wih_b + E, 2 * E, 1, bih_f, bih_b, bhh_f, bhh_b,
        psf, psb, VS, G4, E, 0);

    // w_proj (interleaved cols) = w @ Wih[:,:E]^T
    mma_gemm<<<dim3(10, 8, 2), 256>>>(
        pw, E, Wih_f, Wih_b, 2 * E, 1, nullptr, nullptr, nullptr, nullptr,
        pwf, pwb, B, G4, E, 0);

    // recurrence
    for (int s = 0; s < L; s++)
        lstm_step_mma<<<dim3(10, 8, 2), 256>>>(s, sem);

    // V = relu(Vh @ Wa^T + ba)
    mma_gemm<<<dim3(3, 144, 1), 256>>>(
        pvh, 2 * H, Wa, Wa, 2 * H, 0, ba, ba, nullptr, nullptr,
        Vout, Vout, BL, H, 2 * H, 1);
}

// round 5
// speedup vs baseline: 2.2700x; 2.2700x over previous
#include <cuda_runtime.h>
#include <cuda_bf16.h>
#include <math.h>
#include <stdint.h>

#define B 1024
#define L 18
#define E 300
#define H 300
#define G4 1200
#define KP 304          // H padded to 16
#define NPAD 1280       // G4 padded to 160-tile
#define VS 2186
#define BL (B*L)

#define ABYTES 10240    // 128 rows * 80 B
#define BUFB   23040    // A(10240) + B(160*80=12800)

// ---------------- scratch ----------------
__device__ float g_ag[B * E];
__device__ float g_w [B * E];
__device__ float g_sproj[2][VS * G4];     // interleaved cols n'=4j+gate
__device__ float g_wproj[2][B * G4];      // interleaved
__device__ float g_Vh[BL * 2 * H];
__device__ __nv_bfloat16 g_hh[2][2][B * KP];   // h hi plane
__device__ __nv_bfloat16 g_hl[2][2][B * KP];   // h lo plane
__device__ float g_c[2][B * H];
__device__ __nv_bfloat16 g_Whi[2][NPAD * KP];  // Whh permuted [n'][k] hi
__device__ __nv_bfloat16 g_Wlo[2][NPAD * KP];  // lo

// ---------------- helpers ----------------
__device__ __forceinline__ void spb(float v, float& hi, float& lo) {
    hi = __bfloat162float(__float2bfloat16(v));
    lo = v - hi;
}
__device__ __forceinline__ uint32_t pack2(float x, float y) {
    __nv_bfloat162 v = __floats2bfloat162_rn(x, y);
    return *reinterpret_cast<uint32_t*>(&v);
}
__device__ __forceinline__ void ldsm4(uint32_t* r, uint32_t addr) {
    asm volatile("ldmatrix.sync.aligned.m8n8.x4.shared.b16 {%0,%1,%2,%3}, [%4];"
        : "=r"(r[0]), "=r"(r[1]), "=r"(r[2]), "=r"(r[3]) : "r"(addr));
}
__device__ __forceinline__ void ldsm2(uint32_t& r0, uint32_t& r1, uint32_t addr) {
    asm volatile("ldmatrix.sync.aligned.m8n8.x2.shared.b16 {%0,%1}, [%2];"
        : "=r"(r0), "=r"(r1) : "r"(addr));
}
__device__ __forceinline__ void mma16(float* c, const uint32_t* a, const uint32_t* b) {
    asm volatile("mma.sync.aligned.m16n8k16.row.col.f32.bf16.bf16.f32 "
        "{%0,%1,%2,%3},{%4,%5,%6,%7},{%8,%9},{%0,%1,%2,%3};"
        : "+f"(c[0]), "+f"(c[1]), "+f"(c[2]), "+f"(c[3])
        : "r"(a[0]), "r"(a[1]), "r"(a[2]), "r"(a[3]), "r"(b[0]), "r"(b[1]));
}

// one k16 chunk: 64x40 warp tile, split-3 bf16
__device__ __forceinline__ void mma_chunk(uint32_t Ab, uint32_t Bb, int lane,
                                          int wm, int wn, float (&acc)[4][5][4]) {
    int r8 = lane & 7, sel = lane >> 3;
    int arow = ((sel & 1) << 3) + r8;
    int akoff = (sel >> 1) << 4;
    uint32_t ah[4][4], al[4][4];
#pragma unroll
    for (int im = 0; im < 4; im++) {
        uint32_t addr = Ab + (uint32_t)((wm + im * 16 + arow) * 80 + akoff);
        ldsm4(ah[im], addr);
        ldsm4(al[im], addr + 32);
    }
    uint32_t bh[5][2], bl[5][2];
    int brow = ((sel >> 1) << 3) + r8;
    int bkoff = (sel & 1) << 4;
#pragma unroll
    for (int j2 = 0; j2 < 2; j2++) {
        uint32_t addr = Bb + (uint32_t)((wn + j2 * 16 + brow) * 80 + bkoff);
        uint32_t t[4];
        ldsm4(t, addr);
        bh[2 * j2][0] = t[0]; bh[2 * j2][1] = t[1];
        bh[2 * j2 + 1][0] = t[2]; bh[2 * j2 + 1][1] = t[3];
        ldsm4(t, addr + 32);
        bl[2 * j2][0] = t[0]; bl[2 * j2][1] = t[1];
        bl[2 * j2 + 1][0] = t[2]; bl[2 * j2 + 1][1] = t[3];
    }
    {
        int row2 = lane & 7;
        int koff2 = ((lane >> 3) & 1) << 4;
        uint32_t addr = Bb + (uint32_t)((wn + 32 + row2) * 80 + koff2);
        ldsm2(bh[4][0], bh[4][1], addr);
        ldsm2(bl[4][0], bl[4][1], addr + 32);
    }
#pragma unroll
    for (int n8 = 0; n8 < 5; n8++)
#pragma unroll
        for (int im = 0; im < 4; im++) {
            mma16(acc[im][n8], ah[im], bh[n8]);
            mma16(acc[im][n8], al[im], bh[n8]);
            mma16(acc[im][n8], ah[im], bl[n8]);
        }
}

// ---------------- init ----------------
__global__ void zero_state_kernel() {
    int i = blockIdx.x * blockDim.x + threadIdx.x;
    if (i < 2 * 2 * B * KP) {
        (&g_hh[0][0][0])[i] = __float2bfloat16(0.f);
        (&g_hl[0][0][0])[i] = __float2bfloat16(0.f);
    }
    if (i < 2 * B * H) (&g_c[0][0])[i] = 0.f;
}

// Whh -> permuted interleaved [n'=4j+g][k], padded, bf16 hi/lo planes
__global__ void prep_whh(const float* __restrict__ Wf, const float* __restrict__ Wb) {
    int i = blockIdx.x * blockDim.x + threadIdx.x;
    if (i >= 2 * NPAD * KP) return;
    int dir = i / (NPAD * KP);
    int r = i - dir * (NPAD * KP);
    int np = r / KP, k = r - np * KP;
    float v = 0.f;
    if (np < G4 && k < H) {
        const float* W = dir ? Wb : Wf;
        v = W[(size_t)((np & 3) * H + (np >> 2)) * H + k];
    }
    float hi, lo; spb(v, hi, lo);
    g_Whi[dir][r] = __float2bfloat16(hi);
    g_Wlo[dir][r] = __float2bfloat16(lo);
}

// ---------------- embedding gather ----------------
__global__ void embed_kernel(const int* __restrict__ word,
                             const int* __restrict__ sem,
                             const float* __restrict__ wt,
                             const float* __restrict__ st) {
    int b = blockIdx.x;
    int e = threadIdx.x;
    __shared__ int sidx[L];
    __shared__ int widx;
    if (e < L) sidx[e] = sem[b * L + e];
    if (e == 0) widx = word[b];
    __syncthreads();
    if (e < E) {
        float acc = 0.f;
#pragma unroll
        for (int l = 0; l < L; l++) acc += st[sidx[l] * E + e];
        g_ag[b * E + e] = acc * (1.f / (float)L);
        g_w [b * E + e] = wt[widx * E + e];
    }
}

// ---------------- split-bf16 feed-forward GEMM ----------------
// C = A(MxK,lda) @ Wrow(n)^T + b1 + b2 [relu]; Wrow(n) = imap ? (n&3)*H+(n>>2) : n
// tile 128m x 160n, 8 warps (2m x 4n), warp 64x40.
__global__ void __launch_bounds__(256)
gemm_bf16s(const float* __restrict__ A, int lda,
           const float* __restrict__ W0, const float* __restrict__ W1, int ldw, int imap,
           const float* __restrict__ b10, const float* __restrict__ b11,
           const float* __restrict__ b20, const float* __restrict__ b21,
           float* __restrict__ C0, float* __restrict__ C1,
           int M, int N, int K, int dorelu) {
    int z = blockIdx.z;
    const float* W  = z ? W1 : W0;
    const float* b1 = z ? b11 : b10;
    const float* b2 = z ? b21 : b20;
    float* C        = z ? C1 : C0;

    __shared__ __align__(16) unsigned char smraw[2 * BUFB];
    uint32_t sbase = (uint32_t)__cvta_generic_to_shared(smraw);
    uint32_t* smw = (uint32_t*)smraw;

    int tid = threadIdx.x, lane = tid & 31, wid = tid >> 5;
    int g = lane >> 2, t4 = lane & 3;
    int wm = (wid >> 2) * 64, wn = (wid & 3) * 40;
    int m0 = blockIdx.y * 128, n0 = blockIdx.x * 160;

    float acc[4][5][4];
#pragma unroll
    for (int a = 0; a < 4; a++)
#pragma unroll
        for (int b = 0; b < 5; b++)
#pragma unroll
            for (int c = 0; c < 4; c++) acc[a][b][c] = 0.f;

    int NC = (K + 15) / 16;
    float4 ra[2], rb[3];

    auto loadregs = [&](int kc) {
        int k0 = kc * 16;
#pragma unroll
        for (int q = 0; q < 2; q++) {
            int p = tid + q * 256;
            int row = p >> 2, q4 = p & 3;
            int gm = m0 + row, kk = k0 + q4 * 4;
            float4 v = make_float4(0.f, 0.f, 0.f, 0.f);
            if (gm < M) {
                const float* ap = A + (size_t)gm * lda;
                if (kk + 3 < K) v = *(const float4*)(ap + kk);
                else {
                    if (kk + 0 < K) v.x = ap[kk + 0];
                    if (kk + 1 < K) v.y = ap[kk + 1];
                    if (kk + 2 < K) v.z = ap[kk + 2];
                    if (kk + 3 < K) v.w = ap[kk + 3];
                }
            }
            ra[q] = v;
        }
#pragma unroll
        for (int q = 0; q < 3; q++) {
            int p = tid + q * 256;
            float4 v = make_float4(0.f, 0.f, 0.f, 0.f);
            if (p < 640) {
                int row = p >> 2, q4 = p & 3;
                int nr = n0 + row, kk = k0 + q4 * 4;
                if (nr < N) {
                    int grow = imap ? ((nr & 3) * H + (nr >> 2)) : nr;
                    const float* wp = W + (size_t)grow * ldw;
                    if (kk + 3 < K) v = *(const float4*)(wp + kk);
                    else {
                        if (kk + 0 < K) v.x = wp[kk + 0];
                        if (kk + 1 < K) v.y = wp[kk + 1];
                        if (kk + 2 < K) v.z = wp[kk + 2];
                        if (kk + 3 < K) v.w = wp[kk + 3];
                    }
                }
            }
            rb[q] = v;
        }
    };
    auto storeregs = [&](int buf) {
        uint32_t* Aw = smw + buf * (BUFB / 4);
        uint32_t* Bw = Aw + ABYTES / 4;
#pragma unroll
        for (int q = 0; q < 2; q++) {
            int p = tid + q * 256;
            int row = p >> 2, q4 = p & 3;
            float h0, l0, h1, l1, h2, l2, h3, l3;
            spb(ra[q].x, h0, l0); spb(ra[q].y, h1, l1);
            spb(ra[q].z, h2, l2); spb(ra[q].w, h3, l3);
            Aw[row * 20 + q4 * 2]     = pack2(h0, h1);
            Aw[row * 20 + q4 * 2 + 1] = pack2(h2, h3);
            Aw[row * 20 + 8 + q4 * 2]     = pack2(l0, l1);
            Aw[row * 20 + 8 + q4 * 2 + 1] = pack2(l2, l3);
        }
#pragma unroll
        for (int q = 0; q < 3; q++) {
            int p = tid + q * 256;
            if (p < 640) {
                int row = p >> 2, q4 = p & 3;
                float h0, l0, h1, l1, h2, l2, h3, l3;
                spb(rb[q].x, h0, l0); spb(rb[q].y, h1, l1);
                spb(rb[q].z, h2, l2); spb(rb[q].w, h3, l3);
                Bw[row * 20 + q4 * 2]     = pack2(h0, h1);
                Bw[row * 20 + q4 * 2 + 1] = pack2(h2, h3);
                Bw[row * 20 + 8 + q4 * 2]     = pack2(l0, l1);
                Bw[row * 20 + 8 + q4 * 2 + 1] = pack2(l2, l3);
            }
        }
    };

    loadregs(0);
    storeregs(0);
    __syncthreads();
    for (int kc = 0; kc < NC; kc++) {
        if (kc + 1 < NC) loadregs(kc + 1);
        uint32_t Ab = sbase + (kc & 1) * BUFB;
        mma_chunk(Ab, Ab + ABYTES, lane, wm, wn, acc);
        if (kc + 1 < NC) storeregs((kc + 1) & 1);
        __syncthreads();
    }

    // epilogue (direct global stores)
#pragma unroll
    for (int in8 = 0; in8 < 5; in8++) {
        int n_g = n0 + wn + in8 * 8 + 2 * t4;
        float bv0 = 0.f, bv1 = 0.f;
        if (n_g < N) {
            int i0 = imap ? ((n_g & 3) * H + (n_g >> 2)) : n_g;
            if (b1) bv0 += b1[i0];
            if (b2) bv0 += b2[i0];
        }
        if (n_g + 1 < N) {
            int i1 = imap ? (((n_g + 1) & 3) * H + ((n_g + 1) >> 2)) : (n_g + 1);
            if (b1) bv1 += b1[i1];
            if (b2) bv1 += b2[i1];
        }
#pragma unroll
        for (int im = 0; im < 4; im++) {
            int r0 = m0 + wm + im * 16 + g;
            if (r0 < M) {
                if (n_g < N) {
                    float v = acc[im][in8][0] + bv0;
                    if (dorelu) v = fmaxf(v, 0.f);
                    C[(size_t)r0 * N + n_g] = v;
                }
                if (n_g + 1 < N) {
                    float v = acc[im][in8][1] + bv1;
                    if (dorelu) v = fmaxf(v, 0.f);
                    C[(size_t)r0 * N + n_g + 1] = v;
                }
            }
            int r1 = r0 + 8;
            if (r1 < M) {
                if (n_g < N) {
                    float v = acc[im][in8][2] + bv0;
                    if (dorelu) v = fmaxf(v, 0.f);
                    C[(size_t)r1 * N + n_g] = v;
                }
                if (n_g + 1 < N) {
                    float v = acc[im][in8][3] + bv1;
                    if (dorelu) v = fmaxf(v, 0.f);
                    C[(size_t)r1 * N + n_g + 1] = v;
                }
            }
        }
    }
}

// ---------------- LSTM step: bf16-split mma + fused gates ----------------
// tile 128 b x 160 n' (40 j), grid (8,8,2) = one wave
__global__ void __launch_bounds__(256)
lstm_step_bf16(int st, const int* __restrict__ sem) {
    int dir = blockIdx.z;
    const __nv_bfloat16* Ahp = g_hh[dir][st & 1];
    const __nv_bfloat16* Alp = g_hl[dir][st & 1];
    __nv_bfloat16* Hh = g_hh[dir][(st + 1) & 1];
    __nv_bfloat16* Hl = g_hl[dir][(st + 1) & 1];
    const __nv_bfloat16* Whi = g_Whi[dir];
    const __nv_bfloat16* Wlo = g_Wlo[dir];
    const float* sproj = g_sproj[dir];
    const float* wproj = g_wproj[dir];
    float* cbuf = g_c[dir];
    int t = dir ? (L - 1 - st) : st;

    __shared__ __align__(16) unsigned char smraw[2 * BUFB];
    uint32_t sbase = (uint32_t)__cvta_generic_to_shared(smraw);
    uint32_t* smw = (uint32_t*)smraw;
    float* smf = (float*)smraw;

    int tid = threadIdx.x, lane = tid & 31, wid = tid >> 5;
    int g = lane >> 2, t4 = lane & 3;
    int wmi = wid >> 2;
    int wm = wmi * 64, wn = (wid & 3) * 40;
    int m0 = blockIdx.y * 128, n0 = blockIdx.x * 160;
    int j0 = blockIdx.x * 40;

    float acc[4][5][4];
#pragma unroll
    for (int a = 0; a < 4; a++)
#pragma unroll
        for (int b = 0; b < 5; b++)
#pragma unroll
            for (int c = 0; c < 4; c++) acc[a][b][c] = 0.f;

    const int NC = KP / 16;   // 19
    uint4 ua[2], ub[3];

    auto loadregs = [&](int kc) {
        int k0 = kc * 16;
#pragma unroll
        for (int q = 0; q < 2; q++) {
            int p = tid + q * 256;
            int r512 = p >> 1, half = p & 1;
            int m = r512 & 127, plane = r512 >> 7;
            const __nv_bfloat16* src = plane ? Alp : Ahp;
            ua[q] = *(const uint4*)(src + (size_t)(m0 + m) * KP + k0 + half * 8);
        }
#pragma unroll
        for (int q = 0; q < 3; q++) {
            int p = tid + q * 256;
            if (p < 640) {
                int n = p >> 2, sub = p & 3;
                int plane = sub >> 1, half = sub & 1;
                const __nv_bfloat16* src = plane ? Wlo : Whi;
                ub[q] = *(const uint4*)(src + (size_t)(n0 + n) * KP + k0 + half * 8);
            }
        }
    };
    auto storeregs = [&](int buf) {
        uint4* Aw = (uint4*)(smw + buf * (BUFB / 4));
        uint32_t* Aw32 = smw + buf * (BUFB / 4);
        uint32_t* Bw32 = Aw32 + ABYTES / 4;
#pragma unroll
        for (int q = 0; q < 2; q++) {
            int p = tid + q * 256;
            int r512 = p >> 1, half = p & 1;
            int m = r512 & 127, plane = r512 >> 7;
            *(uint4*)(Aw32 + m * 20 + plane * 8 + half * 4) = ua[q];
        }
#pragma unroll
        for (int q = 0; q < 3; q++) {
            int p = tid + q * 256;
            if (p < 640) {
                int n = p >> 2, sub = p & 3;
                int plane = sub >> 1, half = sub & 1;
                *(uint4*)(Bw32 + n * 20 + plane * 8 + half * 4) = ub[q];
            }
        }
        (void)Aw;
    };

    loadregs(0);
    storeregs(0);
    __syncthreads();
    for (int kc = 0; kc < NC; kc++) {
        if (kc + 1 < NC) loadregs(kc + 1);
        uint32_t Ab = sbase + (kc & 1) * BUFB;
        mma_chunk(Ab, Ab + ABYTES, lane, wm, wn, acc);
        if (kc + 1 < NC) storeregs((kc + 1) & 1);
        __syncthreads();
    }

    // epilogue: preacts -> smem (64 rows x 160 cols, stride 168), gates, state update
    for (int half = 0; half < 2; half++) {
        __syncthreads();
        if (wmi == half) {
#pragma unroll
            for (int in8 = 0; in8 < 5; in8++) {
                int cn = wn + in8 * 8 + 2 * t4;
#pragma unroll
                for (int im = 0; im < 4; im++) {
                    int rl = im * 16 + g;
                    smf[rl * 168 + cn]     = acc[im][in8][0];
                    smf[rl * 168 + cn + 1] = acc[im][in8][1];
                    smf[(rl + 8) * 168 + cn]     = acc[im][in8][2];
                    smf[(rl + 8) * 168 + cn + 1] = acc[im][in8][3];
                }
            }
        }
        __syncthreads();
#pragma unroll
        for (int q = 0; q < 10; q++) {
            int e = tid + q * 256;
            int bl = e / 40, jl = e - bl * 40;
            int j = j0 + jl;
            if (j < H) {
                int b = m0 + half * 64 + bl;
                int idx = sem[b * L + t];
                float4 cs = *(float4*)&smf[bl * 168 + jl * 4];
                float4 sp = *(const float4*)(sproj + (size_t)idx * G4 + 4 * j);
                float4 wp = *(const float4*)(wproj + (size_t)b * G4 + 4 * j);
                float wmul = (idx != 0) ? 1.f : 0.f;
                float gi = cs.x + sp.x + wmul * wp.x;
                float gf = cs.y + sp.y + wmul * wp.y;
                float gg = cs.z + sp.z + wmul * wp.z;
                float go = cs.w + sp.w + wmul * wp.w;
                float ig = 1.f / (1.f + expf(-gi));
                float fg = 1.f / (1.f + expf(-gf));
                float gt = tanhf(gg);
                float og = 1.f / (1.f + expf(-go));
                float cn = fg * cbuf[(size_t)b * H + j] + ig * gt;
                cbuf[(size_t)b * H + j] = cn;
                float h = og * tanhf(cn);
                g_Vh[(size_t)(b * L + t) * (2 * H) + dir * H + j] = h;
                float hh, hl; spb(h, hh, hl);
                Hh[(size_t)b * KP + j] = __float2bfloat16(hh);
                Hl[(size_t)b * KP + j] = __float2bfloat16(hl);
            }
        }
    }
}

// ---------------- launch ----------------
extern "C" void kernel_launch(void* const* d_in, const int* in_sizes, int n_in,
                              void* d_out, int out_size) {
    const int*   word  = (const int*)d_in[0];
    const int*   sem   = (const int*)d_in[1];
    const float* wt    = (const float*)d_in[2];
    const float* st    = (const float*)d_in[3];
    const float* Wih_f = (const float*)d_in[4];
    const float* Whh_f = (const float*)d_in[5];
    const float* bih_f = (const float*)d_in[6];
    const float* bhh_f = (const float*)d_in[7];
    const float* Wih_b = (const float*)d_in[8];
    const float* Whh_b = (const float*)d_in[9];
    const float* bih_b = (const float*)d_in[10];
    const float* bhh_b = (const float*)d_in[11];
    const float* Wa    = (const float*)d_in[12];
    const float* ba    = (const float*)d_in[13];
    const float* Wb    = (const float*)d_in[14];
    const float* bb    = (const float*)d_in[15];

    float* out    = (float*)d_out;
    float* Vout   = out;                       // (B, L, H)
    float* vg_out = out + (size_t)B * L * H;   // (B, E)

    void* p;
    float *pag, *pw, *psf, *psb, *pwf, *pwb, *pvh;
    cudaGetSymbolAddress(&p, g_ag);    pag = (float*)p;
    cudaGetSymbolAddress(&p, g_w);     pw  = (float*)p;
    cudaGetSymbolAddress(&p, g_sproj); psf = (float*)p; psb = psf + (size_t)VS * G4;
    cudaGetSymbolAddress(&p, g_wproj); pwf = (float*)p; pwb = pwf + (size_t)B * G4;
    cudaGetSymbolAddress(&p, g_Vh);    pvh = (float*)p;

    zero_state_kernel<<<(2 * 2 * B * KP + 255) / 256, 256>>>();
    prep_whh<<<(2 * NPAD * KP + 255) / 256, 256>>>(Whh_f, Whh_b);
    embed_kernel<<<B, 320>>>(word, sem, wt, st);

    // v_g = relu(a_g @ Wb^T + bb)
    gemm_bf16s<<<dim3(2, 8, 1), 256>>>(
        pag, E, Wb, Wb, E, 0, bb, bb, nullptr, nullptr,
        vg_out, vg_out, B, E, E, 1);

    // s_proj (interleaved) = sem_table @ Wih[:,E:]^T + bih + bhh
    gemm_bf16s<<<dim3(8, 18, 2), 256>>>(
        st, E, Wih_f + E, Wih_b + E, 2 * E, 1, bih_f, bih_b, bhh_f, bhh_b,
        psf, psb, VS, G4, E, 0);

    // w_proj (interleaved) = w @ Wih[:,:E]^T
    gemm_bf16s<<<dim3(8, 8, 2), 256>>>(
        pw, E, Wih_f, Wih_b, 2 * E, 1, nullptr, nullptr, nullptr, nullptr,
        pwf, pwb, B, G4, E, 0);

    // recurrence
    for (int s = 0; s < L; s++)
        lstm_step_bf16<<<dim3(8, 8, 2), 256>>>(s, sem);

    // V = relu(Vh @ Wa^T + ba)
    gemm_bf16s<<<dim3(2, 144, 1), 256>>>(
        pvh, 2 * H, Wa, Wa, 2 * H, 0, ba, ba, nullptr, nullptr,
        Vout, Vout, BL, H, 2 * H, 1);
}

// round 6
// speedup vs baseline: 2.8179x; 1.2414x over previous
#include <cuda_runtime.h>
#include <cuda_bf16.h>
#include <math.h>
#include <stdint.h>

#define B 1024
#define L 18
#define E 300
#define H 300
#define G4 1200
#define KP 304          // H padded to 16
#define NPAD 1280       // G4 padded to 160-tile
#define VS 2186
#define BL (B*L)

// feed-forward gemm smem layout (80B row stride, proven round 5)
#define ABYTES 10240    // 128 rows * 80 B
#define BUFB   23040    // A(10240) + B(160*80=12800)

// persistent kernel smem: A double-buffer 2*8192, B 19 chunks * 160 rows * 64B
#define PSMEM (16384 + 19*10240)

// ---------------- scratch ----------------
__device__ float g_ag[B * E];
__device__ float g_w [B * E];
__device__ float g_sproj[2][VS * G4];     // interleaved cols n'=4j+gate
__device__ float g_wproj[2][B * G4];      // interleaved
__device__ float g_Vh[BL * 2 * H];
__device__ __nv_bfloat16 g_hh[2][2][B * KP];   // h hi plane [dir][buf]
__device__ __nv_bfloat16 g_hl[2][2][B * KP];   // h lo plane
__device__ __nv_bfloat16 g_Whi[2][NPAD * KP];  // Whh permuted [n'][k] hi
__device__ __nv_bfloat16 g_Wlo[2][NPAD * KP];  // lo
__device__ int g_cnt[2][8];                    // group barriers [dir][m-tile]

// ---------------- helpers ----------------
__device__ __forceinline__ void spb(float v, float& hi, float& lo) {
    hi = __bfloat162float(__float2bfloat16(v));
    lo = v - hi;
}
__device__ __forceinline__ uint32_t pack2(float x, float y) {
    __nv_bfloat162 v = __floats2bfloat162_rn(x, y);
    return *reinterpret_cast<uint32_t*>(&v);
}
__device__ __forceinline__ void ldsm4(uint32_t* r, uint32_t addr) {
    asm volatile("ldmatrix.sync.aligned.m8n8.x4.shared.b16 {%0,%1,%2,%3}, [%4];"
        : "=r"(r[0]), "=r"(r[1]), "=r"(r[2]), "=r"(r[3]) : "r"(addr));
}
__device__ __forceinline__ void ldsm2(uint32_t& r0, uint32_t& r1, uint32_t addr) {
    asm volatile("ldmatrix.sync.aligned.m8n8.x2.shared.b16 {%0,%1}, [%2];"
        : "=r"(r0), "=r"(r1) : "r"(addr));
}
__device__ __forceinline__ void mma16(float* c, const uint32_t* a, const uint32_t* b) {
    asm volatile("mma.sync.aligned.m16n8k16.row.col.f32.bf16.bf16.f32 "
        "{%0,%1,%2,%3},{%4,%5,%6,%7},{%8,%9},{%0,%1,%2,%3};"
        : "+f"(c[0]), "+f"(c[1]), "+f"(c[2]), "+f"(c[3])
        : "r"(a[0]), "r"(a[1]), "r"(a[2]), "r"(a[3]), "r"(b[0]), "r"(b[1]));
}
__device__ __forceinline__ uint4 ldcg4(const void* p) {
    uint4 v;
    asm volatile("ld.global.cg.v4.u32 {%0,%1,%2,%3}, [%4];"
        : "=r"(v.x), "=r"(v.y), "=r"(v.z), "=r"(v.w) : "l"(p));
    return v;
}
// 64B-row-stride swizzle: row r, 16B-segment s (0:hi k0-7, 1:hi k8-15, 2:lo k0-7, 3:lo k8-15)
__device__ __forceinline__ uint32_t swz(int row, int seg) {
    return (uint32_t)(row * 64 + (((seg + (row >> 1)) & 3) << 4));
}
__device__ __forceinline__ float sigf(float x) {
    return __fdividef(1.f, 1.f + __expf(-x));
}
__device__ __forceinline__ float tanhfast(float x) {
    float xc = fminf(fmaxf(x, -15.f), 15.f);
    float e = __expf(2.f * xc);
    return __fdividef(e - 1.f, e + 1.f);
}

// ---------------- mma chunk for 80B-stride layout (feed-forward) ----------------
__device__ __forceinline__ void mma_chunk80(uint32_t Ab, uint32_t Bb, int lane,
                                            int wm, int wn, float (&acc)[4][5][4]) {
    int r8 = lane & 7, sel = lane >> 3;
    int arow = ((sel & 1) << 3) + r8;
    int akoff = (sel >> 1) << 4;
    uint32_t ah[4][4], al[4][4];
#pragma unroll
    for (int im = 0; im < 4; im++) {
        uint32_t addr = Ab + (uint32_t)((wm + im * 16 + arow) * 80 + akoff);
        ldsm4(ah[im], addr);
        ldsm4(al[im], addr + 32);
    }
    uint32_t bh[5][2], bl[5][2];
    int brow = ((sel >> 1) << 3) + r8;
    int bkoff = (sel & 1) << 4;
#pragma unroll
    for (int j2 = 0; j2 < 2; j2++) {
        uint32_t addr = Bb + (uint32_t)((wn + j2 * 16 + brow) * 80 + bkoff);
        uint32_t t[4];
        ldsm4(t, addr);
        bh[2 * j2][0] = t[0]; bh[2 * j2][1] = t[1];
        bh[2 * j2 + 1][0] = t[2]; bh[2 * j2 + 1][1] = t[3];
        ldsm4(t, addr + 32);
        bl[2 * j2][0] = t[0]; bl[2 * j2][1] = t[1];
        bl[2 * j2 + 1][0] = t[2]; bl[2 * j2 + 1][1] = t[3];
    }
    {
        int row2 = lane & 7;
        int koff2 = ((lane >> 3) & 1) << 4;
        uint32_t addr = Bb + (uint32_t)((wn + 32 + row2) * 80 + koff2);
        ldsm2(bh[4][0], bh[4][1], addr);
        ldsm2(bl[4][0], bl[4][1], addr + 32);
    }
#pragma unroll
    for (int n8 = 0; n8 < 5; n8++)
#pragma unroll
        for (int im = 0; im < 4; im++) {
            mma16(acc[im][n8], ah[im], bh[n8]);
            mma16(acc[im][n8], al[im], bh[n8]);
            mma16(acc[im][n8], ah[im], bl[n8]);
        }
}

// ---------------- mma chunk for swizzled 64B layout (persistent) ----------------
__device__ __forceinline__ void mma_chunk64(uint32_t Ab, uint32_t Bb, int lane,
                                            int wm, int wn, float (&acc)[4][5][4]) {
    int r8 = lane & 7, sel = lane >> 3;
    int arow = ((sel & 1) << 3) + r8;
    int akseg = sel >> 1;
    uint32_t ah[4][4], al[4][4];
#pragma unroll
    for (int im = 0; im < 4; im++) {
        int row = wm + im * 16 + arow;
        ldsm4(ah[im], Ab + swz(row, akseg));
        ldsm4(al[im], Ab + swz(row, akseg + 2));
    }
    uint32_t bh[5][2], bl[5][2];
    int brow = ((sel >> 1) << 3) + r8;
    int bkseg = sel & 1;
#pragma unroll
    for (int j2 = 0; j2 < 2; j2++) {
        int row = wn + j2 * 16 + brow;
        uint32_t t[4];
        ldsm4(t, Bb + swz(row, bkseg));
        bh[2 * j2][0] = t[0]; bh[2 * j2][1] = t[1];
        bh[2 * j2 + 1][0] = t[2]; bh[2 * j2 + 1][1] = t[3];
        ldsm4(t, Bb + swz(row, bkseg + 2));
        bl[2 * j2][0] = t[0]; bl[2 * j2][1] = t[1];
        bl[2 * j2 + 1][0] = t[2]; bl[2 * j2 + 1][1] = t[3];
    }
    {
        int row = wn + 32 + (lane & 7);
        int seg = (lane >> 3) & 1;
        ldsm2(bh[4][0], bh[4][1], Bb + swz(row, seg));
        ldsm2(bl[4][0], bl[4][1], Bb + swz(row, seg + 2));
    }
#pragma unroll
    for (int n8 = 0; n8 < 5; n8++)
#pragma unroll
        for (int im = 0; im < 4; im++) {
            mma16(acc[im][n8], ah[im], bh[n8]);
            mma16(acc[im][n8], al[im], bh[n8]);
            mma16(acc[im][n8], ah[im], bl[n8]);
        }
}

// ---------------- init: zero h planes (incl. K pad) + barrier counters ----------------
__global__ void init_kernel() {
    int i = blockIdx.x * blockDim.x + threadIdx.x;
    if (i < 2 * 2 * B * KP) {
        (&g_hh[0][0][0])[i] = __float2bfloat16(0.f);
        (&g_hl[0][0][0])[i] = __float2bfloat16(0.f);
    }
    if (i < 16) (&g_cnt[0][0])[i] = 0;
}

// Whh -> permuted interleaved [n'=4j+g][k], padded, bf16 hi/lo planes
__global__ void prep_whh(const float* __restrict__ Wf, const float* __restrict__ Wb) {
    int i = blockIdx.x * blockDim.x + threadIdx.x;
    if (i >= 2 * NPAD * KP) return;
    int dir = i / (NPAD * KP);
    int r = i - dir * (NPAD * KP);
    int np = r / KP, k = r - np * KP;
    float v = 0.f;
    if (np < G4 && k < H) {
        const float* W = dir ? Wb : Wf;
        v = W[(size_t)((np & 3) * H + (np >> 2)) * H + k];
    }
    float hi, lo; spb(v, hi, lo);
    g_Whi[dir][r] = __float2bfloat16(hi);
    g_Wlo[dir][r] = __float2bfloat16(lo);
}

// ---------------- embedding gather ----------------
__global__ void embed_kernel(const int* __restrict__ word,
                             const int* __restrict__ sem,
                             const float* __restrict__ wt,
                             const float* __restrict__ st) {
    int b = blockIdx.x;
    int e = threadIdx.x;
    __shared__ int sidx[L];
    __shared__ int widx;
    if (e < L) sidx[e] = sem[b * L + e];
    if (e == 0) widx = word[b];
    __syncthreads();
    if (e < E) {
        float acc = 0.f;
#pragma unroll
        for (int l = 0; l < L; l++) acc += st[sidx[l] * E + e];
        g_ag[b * E + e] = acc * (1.f / (float)L);
        g_w [b * E + e] = wt[widx * E + e];
    }
}

// ---------------- feed-forward gemm body (split-bf16, 128x160 tile) ----------------
__device__ __forceinline__ void gemm_body(
    unsigned char* smraw,
    const float* A, int lda, const float* W, int ldw, int imap,
    const float* b1, const float* b2, float* C,
    int M, int N, int K, int dorelu, int bx, int by)
{
    uint32_t sbase = (uint32_t)__cvta_generic_to_shared(smraw);
    uint32_t* smw = (uint32_t*)smraw;

    int tid = threadIdx.x, lane = tid & 31, wid = tid >> 5;
    int g = lane >> 2, t4 = lane & 3;
    int wm = (wid >> 2) * 64, wn = (wid & 3) * 40;
    int m0 = by * 128, n0 = bx * 160;

    float acc[4][5][4];
#pragma unroll
    for (int a = 0; a < 4; a++)
#pragma unroll
        for (int b = 0; b < 5; b++)
#pragma unroll
            for (int c = 0; c < 4; c++) acc[a][b][c] = 0.f;

    int NC = (K + 15) / 16;
    float4 ra[2], rb[3];

    auto loadregs = [&](int kc) {
        int k0 = kc * 16;
#pragma unroll
        for (int q = 0; q < 2; q++) {
            int p = tid + q * 256;
            int row = p >> 2, q4 = p & 3;
            int gm = m0 + row, kk = k0 + q4 * 4;
            float4 v = make_float4(0.f, 0.f, 0.f, 0.f);
            if (gm < M) {
                const float* ap = A + (size_t)gm * lda;
                if (kk + 3 < K) v = *(const float4*)(ap + kk);
                else {
                    if (kk + 0 < K) v.x = ap[kk + 0];
                    if (kk + 1 < K) v.y = ap[kk + 1];
                    if (kk + 2 < K) v.z = ap[kk + 2];
                    if (kk + 3 < K) v.w = ap[kk + 3];
                }
            }
            ra[q] = v;
        }
#pragma unroll
        for (int q = 0; q < 3; q++) {
            int p = tid + q * 256;
            float4 v = make_float4(0.f, 0.f, 0.f, 0.f);
            if (p < 640) {
                int row = p >> 2, q4 = p & 3;
                int nr = n0 + row, kk = k0 + q4 * 4;
                if (nr < N) {
                    int grow = imap ? ((nr & 3) * H + (nr >> 2)) : nr;
                    const float* wp = W + (size_t)grow * ldw;
                    if (kk + 3 < K) v = *(const float4*)(wp + kk);
                    else {
                        if (kk + 0 < K) v.x = wp[kk + 0];
                        if (kk + 1 < K) v.y = wp[kk + 1];
                        if (kk + 2 < K) v.z = wp[kk + 2];
                        if (kk + 3 < K) v.w = wp[kk + 3];
                    }
                }
            }
            rb[q] = v;
        }
    };
    auto storeregs = [&](int buf) {
        uint32_t* Aw = smw + buf * (BUFB / 4);
        uint32_t* Bw = Aw + ABYTES / 4;
#pragma unroll
        for (int q = 0; q < 2; q++) {
            int p = tid + q * 256;
            int row = p >> 2, q4 = p & 3;
            float h0, l0, h1, l1, h2, l2, h3, l3;
            spb(ra[q].x, h0, l0); spb(ra[q].y, h1, l1);
            spb(ra[q].z, h2, l2); spb(ra[q].w, h3, l3);
            Aw[row * 20 + q4 * 2]     = pack2(h0, h1);
            Aw[row * 20 + q4 * 2 + 1] = pack2(h2, h3);
            Aw[row * 20 + 8 + q4 * 2]     = pack2(l0, l1);
            Aw[row * 20 + 8 + q4 * 2 + 1] = pack2(l2, l3);
        }
#pragma unroll
        for (int q = 0; q < 3; q++) {
            int p = tid + q * 256;
            if (p < 640) {
                int row = p >> 2, q4 = p & 3;
                float h0, l0, h1, l1, h2, l2, h3, l3;
                spb(rb[q].x, h0, l0); spb(rb[q].y, h1, l1);
                spb(rb[q].z, h2, l2); spb(rb[q].w, h3, l3);
                Bw[row * 20 + q4 * 2]     = pack2(h0, h1);
                Bw[row * 20 + q4 * 2 + 1] = pack2(h2, h3);
                Bw[row * 20 + 8 + q4 * 2]     = pack2(l0, l1);
                Bw[row * 20 + 8 + q4 * 2 + 1] = pack2(l2, l3);
            }
        }
    };

    loadregs(0);
    storeregs(0);
    __syncthreads();
    for (int kc = 0; kc < NC; kc++) {
        if (kc + 1 < NC) loadregs(kc + 1);
        uint32_t Ab = sbase + (kc & 1) * BUFB;
        mma_chunk80(Ab, Ab + ABYTES, lane, wm, wn, acc);
        if (kc + 1 < NC) storeregs((kc + 1) & 1);
        __syncthreads();
    }

#pragma unroll
    for (int in8 = 0; in8 < 5; in8++) {
        int n_g = n0 + wn + in8 * 8 + 2 * t4;
        float bv0 = 0.f, bv1 = 0.f;
        if (n_g < N) {
            int i0 = imap ? ((n_g & 3) * H + (n_g >> 2)) : n_g;
            if (b1) bv0 += b1[i0];
            if (b2) bv0 += b2[i0];
        }
        if (n_g + 1 < N) {
            int i1 = imap ? (((n_g + 1) & 3) * H + ((n_g + 1) >> 2)) : (n_g + 1);
            if (b1) bv1 += b1[i1];
            if (b2) bv1 += b2[i1];
        }
#pragma unroll
        for (int im = 0; im < 4; im++) {
            int r0 = m0 + wm + im * 16 + g;
            if (r0 < M) {
                if (n_g < N) {
                    float v = acc[im][in8][0] + bv0;
                    if (dorelu) v = fmaxf(v, 0.f);
                    C[(size_t)r0 * N + n_g] = v;
                }
                if (n_g + 1 < N) {
                    float v = acc[im][in8][1] + bv1;
                    if (dorelu) v = fmaxf(v, 0.f);
                    C[(size_t)r0 * N + n_g + 1] = v;
                }
            }
            int r1 = r0 + 8;
            if (r1 < M) {
                if (n_g < N) {
                    float v = acc[im][in8][2] + bv0;
                    if (dorelu) v = fmaxf(v, 0.f);
                    C[(size_t)r1 * N + n_g] = v;
                }
                if (n_g + 1 < N) {
                    float v = acc[im][in8][3] + bv1;
                    if (dorelu) v = fmaxf(v, 0.f);
                    C[(size_t)r1 * N + n_g + 1] = v;
                }
            }
        }
    }
}

// ---------------- merged feed-forward launch: vg + sproj f/b + wproj f/b ----------------
__global__ void __launch_bounds__(256) gemm_ff(
    const float* Wb_, const float* bb_, const float* st,
    const float* Wih_f, const float* Wih_b,
    const float* bih_f, const float* bhh_f,
    const float* bih_b, const float* bhh_b,
    float* vg_out, float* psf, float* psb, float* pwf, float* pwb)
{
    __shared__ __align__(16) unsigned char smraw[2 * BUFB];
    int bid = blockIdx.x;
    if (bid < 16) {
        gemm_body(smraw, g_ag, E, Wb_, E, 0, bb_, nullptr, vg_out,
                  B, E, E, 1, bid & 1, bid >> 1);
    } else if (bid < 160) {
        int r = bid - 16;
        gemm_body(smraw, st, E, Wih_f + E, 2 * E, 1, bih_f, bhh_f, psf,
                  VS, G4, E, 0, r & 7, r >> 3);
    } else if (bid < 304) {
        int r = bid - 160;
        gemm_body(smraw, st, E, Wih_b + E, 2 * E, 1, bih_b, bhh_b, psb,
                  VS, G4, E, 0, r & 7, r >> 3);
    } else if (bid < 368) {
        int r = bid - 304;
        gemm_body(smraw, g_w, E, Wih_f, 2 * E, 1, nullptr, nullptr, pwf,
                  B, G4, E, 0, r & 7, r >> 3);
    } else {
        int r = bid - 368;
        gemm_body(smraw, g_w, E, Wih_b, 2 * E, 1, nullptr, nullptr, pwb,
                  B, G4, E, 0, r & 7, r >> 3);
    }
}

// ---------------- final V gemm ----------------
__global__ void __launch_bounds__(256) gemm_v(
    const float* Wa, const float* ba, float* Vout)
{
    __shared__ __align__(16) unsigned char smraw[2 * BUFB];
    gemm_body(smraw, g_Vh, 2 * H, Wa, 2 * H, 0, ba, nullptr, Vout,
              BL, H, 2 * H, 1, blockIdx.x, blockIdx.y);
}

// ---------------- persistent LSTM: all 18 steps, weights resident in smem ----------------
__global__ void __launch_bounds__(256) lstm_persistent(const int* __restrict__ sem) {
    extern __shared__ __align__(16) unsigned char smraw[];
    uint32_t sbase = (uint32_t)__cvta_generic_to_shared(smraw);
    const int dir = blockIdx.z, mt = blockIdx.y, nt = blockIdx.x;
    const int m0 = mt * 128, n0 = nt * 160;

    int tid = threadIdx.x, lane = tid & 31, wid = tid >> 5;
    int g = lane >> 2, t4 = lane & 3;
    int wm = (wid >> 2) * 64, wn = (wid & 3) * 40;
    int parity = lane & 1;

    uint32_t Abase = sbase;
    uint32_t Bbase = sbase + 16384;

    // load Whh tile into smem once (swizzled)
    {
        const __nv_bfloat16* Whi = g_Whi[dir];
        const __nv_bfloat16* Wlo = g_Wlo[dir];
        for (int p = tid; p < 19 * 640; p += 256) {
            int kc = p / 640, r = p - kc * 640;
            int row = r >> 2, seg = r & 3;
            int plane = seg >> 1, half = seg & 1;
            const __nv_bfloat16* src = plane ? Wlo : Whi;
            uint4 v = *(const uint4*)(src + (size_t)(n0 + row) * KP + kc * 16 + half * 8);
            *(uint4*)(smraw + 16384 + kc * 10240 + swz(row, seg)) = v;
        }
    }
    __syncthreads();

    const float* sproj = g_sproj[dir];
    const float* wproj = g_wproj[dir];

    float cst[4][5];
#pragma unroll
    for (int a = 0; a < 4; a++)
#pragma unroll
        for (int b = 0; b < 5; b++) cst[a][b] = 0.f;

    for (int s = 0; s < L; s++) {
        float acc[4][5][4];
#pragma unroll
        for (int a = 0; a < 4; a++)
#pragma unroll
            for (int b = 0; b < 5; b++)
#pragma unroll
                for (int c = 0; c < 4; c++) acc[a][b][c] = 0.f;

        if (s > 0) {
            const __nv_bfloat16* Ahp = g_hh[dir][(s - 1) & 1];
            const __nv_bfloat16* Alp = g_hl[dir][(s - 1) & 1];
            uint4 ua[2];
            auto loadA = [&](int kc) {
#pragma unroll
                for (int q = 0; q < 2; q++) {
                    int p = tid + q * 256;
                    int row = p >> 2, seg = p & 3;
                    int plane = seg >> 1, half = seg & 1;
                    const __nv_bfloat16* src = plane ? Alp : Ahp;
                    ua[q] = ldcg4(src + (size_t)(m0 + row) * KP + kc * 16 + half * 8);
                }
            };
            auto storeA = [&](int buf) {
#pragma unroll
                for (int q = 0; q < 2; q++) {
                    int p = tid + q * 256;
                    int row = p >> 2, seg = p & 3;
                    *(uint4*)(smraw + buf * 8192 + swz(row, seg)) = ua[q];
                }
            };
            loadA(0); storeA(0);
            __syncthreads();
            for (int kc = 0; kc < 19; kc++) {
                if (kc + 1 < 19) loadA(kc + 1);
                mma_chunk64(Abase + (kc & 1) * 8192, Bbase + kc * 10240,
                            lane, wm, wn, acc);
                if (kc + 1 < 19) storeA((kc + 1) & 1);
                __syncthreads();
            }
        }

        // epilogue: shuffle gate quads together, gates, state update
        int t = dir ? (L - 1 - s) : s;
        __nv_bfloat16* Hh = g_hh[dir][s & 1];
        __nv_bfloat16* Hl = g_hl[dir][s & 1];
#pragma unroll
        for (int im = 0; im < 4; im++) {
            int rowl = wm + im * 16 + g + (parity ? 8 : 0);
            int b = m0 + rowl;
            int idx = sem[b * L + t];
            const float* sp = sproj + (size_t)idx * G4;
            const float* wp = wproj + (size_t)b * G4;
            float wmul = (idx != 0) ? 1.f : 0.f;
#pragma unroll
            for (int n8 = 0; n8 < 5; n8++) {
                float c0 = acc[im][n8][0], c1 = acc[im][n8][1];
                float c2 = acc[im][n8][2], c3 = acc[im][n8][3];
                float s1 = parity ? c0 : c2;
                float s2 = parity ? c1 : c3;
                float r1 = __shfl_xor_sync(0xffffffffu, s1, 1);
                float r2 = __shfl_xor_sync(0xffffffffu, s2, 1);
                float gi, gf, gg, go;
                if (!parity) { gi = c0; gf = c1; gg = r1; go = r2; }
                else         { gi = r1; gf = r2; gg = c2; go = c3; }
                int j = (n0 + wn + n8 * 8 + 2 * t4) >> 2;
                if (j < H) {
                    float4 spv = *(const float4*)(sp + 4 * j);
                    float4 wpv = *(const float4*)(wp + 4 * j);
                    gi += spv.x + wmul * wpv.x;
                    gf += spv.y + wmul * wpv.y;
                    gg += spv.z + wmul * wpv.z;
                    go += spv.w + wmul * wpv.w;
                    float ig = sigf(gi);
                    float fg = sigf(gf);
                    float gt = tanhfast(gg);
                    float og = sigf(go);
                    float cn = fg * cst[im][n8] + ig * gt;
                    cst[im][n8] = cn;
                    float h = og * tanhfast(cn);
                    g_Vh[(size_t)(b * L + t) * (2 * H) + dir * H + j] = h;
                    float hh, hl; spb(h, hh, hl);
                    Hh[(size_t)b * KP + j] = __float2bfloat16(hh);
                    Hl[(size_t)b * KP + j] = __float2bfloat16(hl);
                }
            }
        }

        // group barrier: the 8 n-blocks of this (dir, m-tile) must finish step s
        if (s < L - 1) {
            __threadfence();
            __syncthreads();
            if (tid == 0) {
                atomicAdd(&g_cnt[dir][mt], 1);
                int target = 8 * (s + 1);
                while (atomicAdd(&g_cnt[dir][mt], 0) < target) { }
            }
            __syncthreads();
        }
    }
}

// ---------------- launch ----------------
extern "C" void kernel_launch(void* const* d_in, const int* in_sizes, int n_in,
                              void* d_out, int out_size) {
    const int*   word  = (const int*)d_in[0];
    const int*   sem   = (const int*)d_in[1];
    const float* wt    = (const float*)d_in[2];
    const float* st    = (const float*)d_in[3];
    const float* Wih_f = (const float*)d_in[4];
    const float* Whh_f = (const float*)d_in[5];
    const float* bih_f = (const float*)d_in[6];
    const float* bhh_f = (const float*)d_in[7];
    const float* Wih_b = (const float*)d_in[8];
    const float* Whh_b = (const float*)d_in[9];
    const float* bih_b = (const float*)d_in[10];
    const float* bhh_b = (const float*)d_in[11];
    const float* Wa    = (const float*)d_in[12];
    const float* ba    = (const float*)d_in[13];
    const float* Wb    = (const float*)d_in[14];
    const float* bb    = (const float*)d_in[15];

    float* out    = (float*)d_out;
    float* Vout   = out;                       // (B, L, H)
    float* vg_out = out + (size_t)B * L * H;   // (B, E)

    void* p;
    float *psf, *psb, *pwf, *pwb;
    cudaGetSymbolAddress(&p, g_sproj); psf = (float*)p; psb = psf + (size_t)VS * G4;
    cudaGetSymbolAddress(&p, g_wproj); pwf = (float*)p; pwb = pwf + (size_t)B * G4;

    cudaFuncSetAttribute(lstm_persistent,
                         cudaFuncAttributeMaxDynamicSharedMemorySize, PSMEM);

    init_kernel<<<(2 * 2 * B * KP + 255) / 256, 256>>>();
    prep_whh<<<(2 * NPAD * KP + 255) / 256, 256>>>(Whh_f, Whh_b);
    embed_kernel<<<B, 320>>>(word, sem, wt, st);

    // all feed-forward gemms in one launch
    gemm_ff<<<432, 256>>>(Wb, bb, st, Wih_f, Wih_b,
                          bih_f, bhh_f, bih_b, bhh_b,
                          vg_out, psf, psb, pwf, pwb);

    // whole recurrence in one persistent launch
    lstm_persistent<<<dim3(8, 8, 2), 256, PSMEM>>>(sem);

    // V = relu(Vh @ Wa^T + ba)
    gemm_v<<<dim3(2, 144), 256>>>(Wa, ba, Vout);
}

// round 7
// speedup vs baseline: 3.3327x; 1.1827x over previous
#include <cuda_runtime.h>
#include <cuda_bf16.h>
#include <math.h>
#include <stdint.h>

#define B 1024
#define L 18
#define E 300
#define H 300
#define G4 1200
#define KP 304          // H padded to 16
#define NPAD 1280       // G4 padded to 160-tile
#define VS 2186
#define BL (B*L)

#define ABYTES 10240    // 128 rows * 80 B
#define BUFB   23040    // A(10240) + B(160*80=12800)
#define PSMEM (16384 + 19*10240)

// ---------------- scratch ----------------
__device__ float g_ag[B * E];
__device__ float g_w [B * E];
__device__ float g_sproj[2][VS * G4];     // interleaved cols n'=4j+gate
__device__ float g_wproj[2][B * G4];      // interleaved
__device__ float g_Vh[BL * 2 * H];
__device__ uint32_t g_hpk[2][2][B * KP];  // h packed (hi,lo) bf16x2 [dir][buf]
__device__ __nv_bfloat16 g_Whi[2][NPAD * KP];  // Whh permuted [n'][k] hi
__device__ __nv_bfloat16 g_Wlo[2][NPAD * KP];  // lo
__device__ int g_cnt[2][8];                    // group barriers [dir][m-tile]

// ---------------- helpers ----------------
__device__ __forceinline__ void spb(float v, float& hi, float& lo) {
    hi = __bfloat162float(__float2bfloat16(v));
    lo = v - hi;
}
__device__ __forceinline__ uint32_t pack2(float x, float y) {
    __nv_bfloat162 v = __floats2bfloat162_rn(x, y);
    return *reinterpret_cast<uint32_t*>(&v);
}
__device__ __forceinline__ void ldsm4(uint32_t* r, uint32_t addr) {
    asm volatile("ldmatrix.sync.aligned.m8n8.x4.shared.b16 {%0,%1,%2,%3}, [%4];"
        : "=r"(r[0]), "=r"(r[1]), "=r"(r[2]), "=r"(r[3]) : "r"(addr));
}
__device__ __forceinline__ void ldsm2(uint32_t& r0, uint32_t& r1, uint32_t addr) {
    asm volatile("ldmatrix.sync.aligned.m8n8.x2.shared.b16 {%0,%1}, [%2];"
        : "=r"(r0), "=r"(r1) : "r"(addr));
}
__device__ __forceinline__ void mma16(float* c, const uint32_t* a, const uint32_t* b) {
    asm volatile("mma.sync.aligned.m16n8k16.row.col.f32.bf16.bf16.f32 "
        "{%0,%1,%2,%3},{%4,%5,%6,%7},{%8,%9},{%0,%1,%2,%3};"
        : "+f"(c[0]), "+f"(c[1]), "+f"(c[2]), "+f"(c[3])
        : "r"(a[0]), "r"(a[1]), "r"(a[2]), "r"(a[3]), "r"(b[0]), "r"(b[1]));
}
__device__ __forceinline__ uint4 ldcg4(const void* p) {
    uint4 v;
    asm volatile("ld.global.cg.v4.u32 {%0,%1,%2,%3}, [%4];"
        : "=r"(v.x), "=r"(v.y), "=r"(v.z), "=r"(v.w) : "l"(p));
    return v;
}
__device__ __forceinline__ uint32_t swz(int row, int seg) {
    return (uint32_t)(row * 64 + (((seg + (row >> 1)) & 3) << 4));
}
__device__ __forceinline__ float sigf(float x) {
    return __fdividef(1.f, 1.f + __expf(-x));
}
__device__ __forceinline__ float tanhfast(float x) {
    float xc = fminf(fmaxf(x, -15.f), 15.f);
    float e = __expf(2.f * xc);
    return __fdividef(e - 1.f, e + 1.f);
}

// ---------------- mma chunk, warp tile 32x40, 80B-stride layout ----------------
__device__ __forceinline__ void mma_chunk80(uint32_t Ab, uint32_t Bb, int lane,
                                            int wm, int wn, float (&acc)[2][5][4]) {
    int r8 = lane & 7, sel = lane >> 3;
    int arow = ((sel & 1) << 3) + r8;
    int akoff = (sel >> 1) << 4;
    uint32_t ah[2][4], al[2][4];
#pragma unroll
    for (int im = 0; im < 2; im++) {
        uint32_t addr = Ab + (uint32_t)((wm + im * 16 + arow) * 80 + akoff);
        ldsm4(ah[im], addr);
        ldsm4(al[im], addr + 32);
    }
    uint32_t bh[5][2], bl[5][2];
    int brow = ((sel >> 1) << 3) + r8;
    int bkoff = (sel & 1) << 4;
#pragma unroll
    for (int j2 = 0; j2 < 2; j2++) {
        uint32_t addr = Bb + (uint32_t)((wn + j2 * 16 + brow) * 80 + bkoff);
        uint32_t t[4];
        ldsm4(t, addr);
        bh[2 * j2][0] = t[0]; bh[2 * j2][1] = t[1];
        bh[2 * j2 + 1][0] = t[2]; bh[2 * j2 + 1][1] = t[3];
        ldsm4(t, addr + 32);
        bl[2 * j2][0] = t[0]; bl[2 * j2][1] = t[1];
        bl[2 * j2 + 1][0] = t[2]; bl[2 * j2 + 1][1] = t[3];
    }
    {
        int row2 = lane & 7;
        int koff2 = ((lane >> 3) & 1) << 4;
        uint32_t addr = Bb + (uint32_t)((wn + 32 + row2) * 80 + koff2);
        ldsm2(bh[4][0], bh[4][1], addr);
        ldsm2(bl[4][0], bl[4][1], addr + 32);
    }
#pragma unroll
    for (int n8 = 0; n8 < 5; n8++)
#pragma unroll
        for (int im = 0; im < 2; im++) {
            mma16(acc[im][n8], ah[im], bh[n8]);
            mma16(acc[im][n8], al[im], bh[n8]);
            mma16(acc[im][n8], ah[im], bl[n8]);
        }
}

// ---------------- mma chunk, warp tile 32x40, swizzled 64B layout ----------------
__device__ __forceinline__ void mma_chunk64(uint32_t Ab, uint32_t Bb, int lane,
                                            int wm, int wn, float (&acc)[2][5][4]) {
    int r8 = lane & 7, sel = lane >> 3;
    int arow = ((sel & 1) << 3) + r8;
    int akseg = sel >> 1;
    uint32_t ah[2][4], al[2][4];
#pragma unroll
    for (int im = 0; im < 2; im++) {
        int row = wm + im * 16 + arow;
        ldsm4(ah[im], Ab + swz(row, akseg));
        ldsm4(al[im], Ab + swz(row, akseg + 2));
    }
    uint32_t bh[5][2], bl[5][2];
    int brow = ((sel >> 1) << 3) + r8;
    int bkseg = sel & 1;
#pragma unroll
    for (int j2 = 0; j2 < 2; j2++) {
        int row = wn + j2 * 16 + brow;
        uint32_t t[4];
        ldsm4(t, Bb + swz(row, bkseg));
        bh[2 * j2][0] = t[0]; bh[2 * j2][1] = t[1];
        bh[2 * j2 + 1][0] = t[2]; bh[2 * j2 + 1][1] = t[3];
        ldsm4(t, Bb + swz(row, bkseg + 2));
        bl[2 * j2][0] = t[0]; bl[2 * j2][1] = t[1];
        bl[2 * j2 + 1][0] = t[2]; bl[2 * j2 + 1][1] = t[3];
    }
    {
        int row = wn + 32 + (lane & 7);
        int seg = (lane >> 3) & 1;
        ldsm2(bh[4][0], bh[4][1], Bb + swz(row, seg));
        ldsm2(bl[4][0], bl[4][1], Bb + swz(row, seg + 2));
    }
#pragma unroll
    for (int n8 = 0; n8 < 5; n8++)
#pragma unroll
        for (int im = 0; im < 2; im++) {
            mma16(acc[im][n8], ah[im], bh[n8]);
            mma16(acc[im][n8], al[im], bh[n8]);
            mma16(acc[im][n8], ah[im], bl[n8]);
        }
}

// ---------------- init ----------------
__global__ void init_kernel() {
    int i = blockIdx.x * blockDim.x + threadIdx.x;
    if (i < 2 * 2 * B * KP) (&g_hpk[0][0][0])[i] = 0u;
    if (i < 16) (&g_cnt[0][0])[i] = 0;
}

__global__ void prep_whh(const float* __restrict__ Wf, const float* __restrict__ Wb) {
    int i = blockIdx.x * blockDim.x + threadIdx.x;
    if (i >= 2 * NPAD * KP) return;
    int dir = i / (NPAD * KP);
    int r = i - dir * (NPAD * KP);
    int np = r / KP, k = r - np * KP;
    float v = 0.f;
    if (np < G4 && k < H) {
        const float* W = dir ? Wb : Wf;
        v = W[(size_t)((np & 3) * H + (np >> 2)) * H + k];
    }
    float hi, lo; spb(v, hi, lo);
    g_Whi[dir][r] = __float2bfloat16(hi);
    g_Wlo[dir][r] = __float2bfloat16(lo);
}

__global__ void embed_kernel(const int* __restrict__ word,
                             const int* __restrict__ sem,
                             const float* __restrict__ wt,
                             const float* __restrict__ st) {
    int b = blockIdx.x;
    int e = threadIdx.x;
    __shared__ int sidx[L];
    __shared__ int widx;
    if (e < L) sidx[e] = sem[b * L + e];
    if (e == 0) widx = word[b];
    __syncthreads();
    if (e < E) {
        float acc = 0.f;
#pragma unroll
        for (int l = 0; l < L; l++) acc += st[sidx[l] * E + e];
        g_ag[b * E + e] = acc * (1.f / (float)L);
        g_w [b * E + e] = wt[widx * E + e];
    }
}

// ---------------- feed-forward gemm body (split-bf16, 128x160 tile, 512 thr) ----------------
__device__ __forceinline__ void gemm_body(
    unsigned char* smraw,
    const float* A, int lda, const float* W, int ldw, int imap,
    const float* b1, const float* b2, float* C,
    int M, int N, int K, int dorelu, int bx, int by)
{
    uint32_t sbase = (uint32_t)__cvta_generic_to_shared(smraw);
    uint32_t* smw = (uint32_t*)smraw;

    int tid = threadIdx.x, lane = tid & 31, wid = tid >> 5;
    int g = lane >> 2, t4 = lane & 3;
    int wm = (wid >> 2) * 32, wn = (wid & 3) * 40;
    int m0 = by * 128, n0 = bx * 160;

    float acc[2][5][4];
#pragma unroll
    for (int a = 0; a < 2; a++)
#pragma unroll
        for (int b = 0; b < 5; b++)
#pragma unroll
            for (int c = 0; c < 4; c++) acc[a][b][c] = 0.f;

    int NC = (K + 15) / 16;
    float4 ra, rb[2];

    auto loadregs = [&](int kc) {
        int k0 = kc * 16;
        {
            int row = tid >> 2, q4 = tid & 3;
            int gm = m0 + row, kk = k0 + q4 * 4;
            float4 v = make_float4(0.f, 0.f, 0.f, 0.f);
            if (gm < M) {
                const float* ap = A + (size_t)gm * lda;
                if (kk + 3 < K) v = *(const float4*)(ap + kk);
                else {
                    if (kk + 0 < K) v.x = ap[kk + 0];
                    if (kk + 1 < K) v.y = ap[kk + 1];
                    if (kk + 2 < K) v.z = ap[kk + 2];
                    if (kk + 3 < K) v.w = ap[kk + 3];
                }
            }
            ra = v;
        }
#pragma unroll
        for (int q = 0; q < 2; q++) {
            int p = tid + q * 512;
            float4 v = make_float4(0.f, 0.f, 0.f, 0.f);
            if (p < 640) {
                int row = p >> 2, q4 = p & 3;
                int nr = n0 + row, kk = k0 + q4 * 4;
                if (nr < N) {
                    int grow = imap ? ((nr & 3) * H + (nr >> 2)) : nr;
                    const float* wp = W + (size_t)grow * ldw;
                    if (kk + 3 < K) v = *(const float4*)(wp + kk);
                    else {
                        if (kk + 0 < K) v.x = wp[kk + 0];
                        if (kk + 1 < K) v.y = wp[kk + 1];
                        if (kk + 2 < K) v.z = wp[kk + 2];
                        if (kk + 3 < K) v.w = wp[kk + 3];
                    }
                }
            }
            rb[q] = v;
        }
    };
    auto storeregs = [&](int buf) {
        uint32_t* Aw = smw + buf * (BUFB / 4);
        uint32_t* Bw = Aw + ABYTES / 4;
        {
            int row = tid >> 2, q4 = tid & 3;
            float h0, l0, h1, l1, h2, l2, h3, l3;
            spb(ra.x, h0, l0); spb(ra.y, h1, l1);
            spb(ra.z, h2, l2); spb(ra.w, h3, l3);
            Aw[row * 20 + q4 * 2]     = pack2(h0, h1);
            Aw[row * 20 + q4 * 2 + 1] = pack2(h2, h3);
            Aw[row * 20 + 8 + q4 * 2]     = pack2(l0, l1);
            Aw[row * 20 + 8 + q4 * 2 + 1] = pack2(l2, l3);
        }
#pragma unroll
        for (int q = 0; q < 2; q++) {
            int p = tid + q * 512;
            if (p < 640) {
                int row = p >> 2, q4 = p & 3;
                float h0, l0, h1, l1, h2, l2, h3, l3;
                spb(rb[q].x, h0, l0); spb(rb[q].y, h1, l1);
                spb(rb[q].z, h2, l2); spb(rb[q].w, h3, l3);
                Bw[row * 20 + q4 * 2]     = pack2(h0, h1);
                Bw[row * 20 + q4 * 2 + 1] = pack2(h2, h3);
                Bw[row * 20 + 8 + q4 * 2]     = pack2(l0, l1);
                Bw[row * 20 + 8 + q4 * 2 + 1] = pack2(l2, l3);
            }
        }
    };

    loadregs(0);
    storeregs(0);
    __syncthreads();
    for (int kc = 0; kc < NC; kc++) {
        if (kc + 1 < NC) loadregs(kc + 1);
        uint32_t Ab = sbase + (kc & 1) * BUFB;
        mma_chunk80(Ab, Ab + ABYTES, lane, wm, wn, acc);
        if (kc + 1 < NC) storeregs((kc + 1) & 1);
        __syncthreads();
    }

#pragma unroll
    for (int in8 = 0; in8 < 5; in8++) {
        int n_g = n0 + wn + in8 * 8 + 2 * t4;
        float bv0 = 0.f, bv1 = 0.f;
        if (n_g < N) {
            int i0 = imap ? ((n_g & 3) * H + (n_g >> 2)) : n_g;
            if (b1) bv0 += b1[i0];
            if (b2) bv0 += b2[i0];
        }
        if (n_g + 1 < N) {
            int i1 = imap ? (((n_g + 1) & 3) * H + ((n_g + 1) >> 2)) : (n_g + 1);
            if (b1) bv1 += b1[i1];
            if (b2) bv1 += b2[i1];
        }
#pragma unroll
        for (int im = 0; im < 2; im++) {
            int r0 = m0 + wm + im * 16 + g;
            if (r0 < M) {
                if (n_g < N) {
                    float v = acc[im][in8][0] + bv0;
                    if (dorelu) v = fmaxf(v, 0.f);
                    C[(size_t)r0 * N + n_g] = v;
                }
                if (n_g + 1 < N) {
                    float v = acc[im][in8][1] + bv1;
                    if (dorelu) v = fmaxf(v, 0.f);
                    C[(size_t)r0 * N + n_g + 1] = v;
                }
            }
            int r1 = r0 + 8;
            if (r1 < M) {
                if (n_g < N) {
                    float v = acc[im][in8][2] + bv0;
                    if (dorelu) v = fmaxf(v, 0.f);
                    C[(size_t)r1 * N + n_g] = v;
                }
                if (n_g + 1 < N) {
                    float v = acc[im][in8][3] + bv1;
                    if (dorelu) v = fmaxf(v, 0.f);
                    C[(size_t)r1 * N + n_g + 1] = v;
                }
            }
        }
    }
}

// ---------------- merged feed-forward launch ----------------
__global__ void __launch_bounds__(512) gemm_ff(
    const float* Wb_, const float* bb_, const float* st,
    const float* Wih_f, const float* Wih_b,
    const float* bih_f, const float* bhh_f,
    const float* bih_b, const float* bhh_b,
    float* vg_out, float* psf, float* psb, float* pwf, float* pwb)
{
    __shared__ __align__(16) unsigned char smraw[2 * BUFB];
    int bid = blockIdx.x;
    if (bid < 16) {
        gemm_body(smraw, g_ag, E, Wb_, E, 0, bb_, nullptr, vg_out,
                  B, E, E, 1, bid & 1, bid >> 1);
    } else if (bid < 160) {
        int r = bid - 16;
        gemm_body(smraw, st, E, Wih_f + E, 2 * E, 1, bih_f, bhh_f, psf,
                  VS, G4, E, 0, r & 7, r >> 3);
    } else if (bid < 304) {
        int r = bid - 160;
        gemm_body(smraw, st, E, Wih_b + E, 2 * E, 1, bih_b, bhh_b, psb,
                  VS, G4, E, 0, r & 7, r >> 3);
    } else if (bid < 368) {
        int r = bid - 304;
        gemm_body(smraw, g_w, E, Wih_f, 2 * E, 1, nullptr, nullptr, pwf,
                  B, G4, E, 0, r & 7, r >> 3);
    } else {
        int r = bid - 368;
        gemm_body(smraw, g_w, E, Wih_b, 2 * E, 1, nullptr, nullptr, pwb,
                  B, G4, E, 0, r & 7, r >> 3);
    }
}

__global__ void __launch_bounds__(512) gemm_v(
    const float* Wa, const float* ba, float* Vout)
{
    __shared__ __align__(16) unsigned char smraw[2 * BUFB];
    gemm_body(smraw, g_Vh, 2 * H, Wa, 2 * H, 0, ba, nullptr, Vout,
              BL, H, 2 * H, 1, blockIdx.x, blockIdx.y);
}

// ---------------- persistent LSTM ----------------
__global__ void __launch_bounds__(512) lstm_persistent(const int* __restrict__ sem) {
    extern __shared__ __align__(16) unsigned char smraw[];
    uint32_t sbase = (uint32_t)__cvta_generic_to_shared(smraw);
    const int dir = blockIdx.z, mt = blockIdx.y, nt = blockIdx.x;
    const int m0 = mt * 128, n0 = nt * 160;

    int tid = threadIdx.x, lane = tid & 31, wid = tid >> 5;
    int g = lane >> 2, t4 = lane & 3;
    int wm = (wid >> 2) * 32, wn = (wid & 3) * 40;
    int parity = lane & 1;

    uint32_t Abase = sbase;
    uint32_t Bbase = sbase + 16384;

    // load Whh tile into smem once (swizzled)
    {
        const __nv_bfloat16* Whi = g_Whi[dir];
        const __nv_bfloat16* Wlo = g_Wlo[dir];
        for (int p = tid; p < 19 * 640; p += 512) {
            int kc = p / 640, r = p - kc * 640;
            int row = r >> 2, seg = r & 3;
            int plane = seg >> 1, half = seg & 1;
            const __nv_bfloat16* src = plane ? Wlo : Whi;
            uint4 v = *(const uint4*)(src + (size_t)(n0 + row) * KP + kc * 16 + half * 8);
            *(uint4*)(smraw + 16384 + kc * 10240 + swz(row, seg)) = v;
        }
    }
    __syncthreads();

    const float* sproj = g_sproj[dir];
    const float* wproj = g_wproj[dir];

    float cst[2][5];
#pragma unroll
    for (int a = 0; a < 2; a++)
#pragma unroll
        for (int b = 0; b < 5; b++) cst[a][b] = 0.f;

    for (int s = 0; s < L; s++) {
        float acc[2][5][4];
#pragma unroll
        for (int a = 0; a < 2; a++)
#pragma unroll
            for (int b = 0; b < 5; b++)
#pragma unroll
                for (int c = 0; c < 4; c++) acc[a][b][c] = 0.f;

        if (s > 0) {
            const uint32_t* Apk = g_hpk[dir][(s - 1) & 1];
            uint4 ua;
            int arow = tid >> 2, akq = tid & 3;
            auto loadA = [&](int kc) {
                ua = ldcg4(Apk + (size_t)(m0 + arow) * KP + kc * 16 + akq * 4);
            };
            auto storeA = [&](int buf) {
                uint32_t hiA = __byte_perm(ua.x, ua.y, 0x5410);
                uint32_t hiB = __byte_perm(ua.z, ua.w, 0x5410);
                uint32_t loA = __byte_perm(ua.x, ua.y, 0x7632);
                uint32_t loB = __byte_perm(ua.z, ua.w, 0x7632);
                uint32_t base = (uint32_t)(buf * 8192);
                *(uint2*)(smraw + base + swz(arow, akq >> 1) + (akq & 1) * 8)
                    = make_uint2(hiA, hiB);
                *(uint2*)(smraw + base + swz(arow, (akq >> 1) + 2) + (akq & 1) * 8)
                    = make_uint2(loA, loB);
            };
            loadA(0); storeA(0);
            __syncthreads();
            for (int kc = 0; kc < 19; kc++) {
                if (kc + 1 < 19) loadA(kc + 1);
                mma_chunk64(Abase + (kc & 1) * 8192, Bbase + kc * 10240,
                            lane, wm, wn, acc);
                if (kc + 1 < 19) storeA((kc + 1) & 1);
                __syncthreads();
            }
        }

        // epilogue
        int t = dir ? (L - 1 - s) : s;
        uint32_t* Hpk = g_hpk[dir][s & 1];
#pragma unroll
        for (int im = 0; im < 2; im++) {
            int rowl = wm + im * 16 + g + (parity ? 8 : 0);
            int b = m0 + rowl;
            int idx = sem[b * L + t];
            const float* sp = sproj + (size_t)idx * G4;
            const float* wp = wproj + (size_t)b * G4;
            float wmul = (idx != 0) ? 1.f : 0.f;
#pragma unroll
            for (int n8 = 0; n8 < 5; n8++) {
                float c0 = acc[im][n8][0], c1 = acc[im][n8][1];
                float c2 = acc[im][n8][2], c3 = acc[im][n8][3];
                float s1 = parity ? c0 : c2;
                float s2 = parity ? c1 : c3;
                float r1 = __shfl_xor_sync(0xffffffffu, s1, 1);
                float r2 = __shfl_xor_sync(0xffffffffu, s2, 1);
                float gi, gf, gg, go;
                if (!parity) { gi = c0; gf = c1; gg = r1; go = r2; }
                else         { gi = r1; gf = r2; gg = c2; go = c3; }
                int j = (n0 + wn + n8 * 8 + 2 * t4) >> 2;
                if (j < H) {
                    float4 spv = *(const float4*)(sp + 4 * j);
                    float4 wpv = *(const float4*)(wp + 4 * j);
                    gi += spv.x + wmul * wpv.x;
                    gf += spv.y + wmul * wpv.y;
                    gg += spv.z + wmul * wpv.z;
                    go += spv.w + wmul * wpv.w;
                    float ig = sigf(gi);
                    float fg = sigf(gf);
                    float gt = tanhfast(gg);
                    float og = sigf(go);
                    float cn = fg * cst[im][n8] + ig * gt;
                    cst[im][n8] = cn;
                    float h = og * tanhfast(cn);
                    g_Vh[(size_t)(b * L + t) * (2 * H) + dir * H + j] = h;
                    float hh, hl; spb(h, hh, hl);
                    Hpk[(size_t)b * KP + j] = pack2(hh, hl);
                }
            }
        }

        // group barrier
        if (s < L - 1) {
            __threadfence();
            __syncthreads();
            if (tid == 0) {
                atomicAdd(&g_cnt[dir][mt], 1);
                int target = 8 * (s + 1);
                const int* cp = &g_cnt[dir][mt];
                while (true) {
                    int v;
                    asm volatile("ld.global.cg.b32 %0, [%1];" : "=r"(v) : "l"(cp));
                    if (v >= target) break;
                    __nanosleep(100);
                }
            }
            __syncthreads();
        }
    }
}

// ---------------- launch ----------------
extern "C" void kernel_launch(void* const* d_in, const int* in_sizes, int n_in,
                              void* d_out, int out_size) {
    const int*   word  = (const int*)d_in[0];
    const int*   sem   = (const int*)d_in[1];
    const float* wt    = (const float*)d_in[2];
    const float* st    = (const float*)d_in[3];
    const float* Wih_f = (const float*)d_in[4];
    const float* Whh_f = (const float*)d_in[5];
    const float* bih_f = (const float*)d_in[6];
    const float* bhh_f = (const float*)d_in[7];
    const float* Wih_b = (const float*)d_in[8];
    const float* Whh_b = (const float*)d_in[9];
    const float* bih_b = (const float*)d_in[10];
    const float* bhh_b = (const float*)d_in[11];
    const float* Wa    = (const float*)d_in[12];
    const float* ba    = (const float*)d_in[13];
    const float* Wb    = (const float*)d_in[14];
    const float* bb    = (const float*)d_in[15];

    float* out    = (float*)d_out;
    float* Vout   = out;
    float* vg_out = out + (size_t)B * L * H;

    void* p;
    float *psf, *psb, *pwf, *pwb;
    cudaGetSymbolAddress(&p, g_sproj); psf = (float*)p; psb = psf + (size_t)VS * G4;
    cudaGetSymbolAddress(&p, g_wproj); pwf = (float*)p; pwb = pwf + (size_t)B * G4;

    cudaFuncSetAttribute(lstm_persistent,
                         cudaFuncAttributeMaxDynamicSharedMemorySize, PSMEM);

    init_kernel<<<(2 * 2 * B * KP + 255) / 256, 256>>>();
    prep_whh<<<(2 * NPAD * KP + 255) / 256, 256>>>(Whh_f, Whh_b);
    embed_kernel<<<B, 320>>>(word, sem, wt, st);

    gemm_ff<<<432, 512>>>(Wb, bb, st, Wih_f, Wih_b,
                          bih_f, bhh_f, bih_b, bhh_b,
                          vg_out, psf, psb, pwf, pwb);

    lstm_persistent<<<dim3(8, 8, 2), 512, PSMEM>>>(sem);

    gemm_v<<<dim3(2, 144), 512>>>(Wa, ba, Vout);
}

// round 8
// speedup vs baseline: 3.5816x; 1.0747x over previous
#include <cuda_runtime.h>
#include <cuda_bf16.h>
#include <math.h>
#include <stdint.h>

#define B 1024
#define L 18
#define E 300
#define H 300
#define G4 1200
#define KP 304          // H padded to 16
#define NPAD 1280       // G4 padded to 160-tile
#define VS 2186
#define BL (B*L)

#define ABYTES 10240    // 128 rows * 80 B
#define BUFB   23040    // A(10240) + B(160*80=12800)
#define FFSMEM (4*BUFB) // 92160, 4-deep sub-buffer ring
#define PSMEM (4*8192 + 19*10240)   // 227328

// ---------------- scratch ----------------
__device__ float g_ag[B * E];
__device__ float g_w [B * E];
__device__ float g_sproj[2][VS * G4];     // interleaved cols n'=4j+gate
__device__ float g_wproj[2][B * G4];      // interleaved
__device__ float g_Vh[BL * 2 * H];
__device__ uint32_t g_hpk[2][2][B * KP];  // h packed (hi,lo) bf16x2 [dir][buf]
__device__ __nv_bfloat16 g_Whi[2][NPAD * KP];  // Whh permuted [n'][k] hi
__device__ __nv_bfloat16 g_Wlo[2][NPAD * KP];  // lo
__device__ int g_cnt[2][8];                    // group barriers [dir][m-tile]

// ---------------- helpers ----------------
__device__ __forceinline__ void spb(float v, float& hi, float& lo) {
    hi = __bfloat162float(__float2bfloat16(v));
    lo = v - hi;
}
__device__ __forceinline__ uint32_t pack2(float x, float y) {
    __nv_bfloat162 v = __floats2bfloat162_rn(x, y);
    return *reinterpret_cast<uint32_t*>(&v);
}
__device__ __forceinline__ void ldsm4(uint32_t* r, uint32_t addr) {
    asm volatile("ldmatrix.sync.aligned.m8n8.x4.shared.b16 {%0,%1,%2,%3}, [%4];"
        : "=r"(r[0]), "=r"(r[1]), "=r"(r[2]), "=r"(r[3]) : "r"(addr));
}
__device__ __forceinline__ void ldsm2(uint32_t& r0, uint32_t& r1, uint32_t addr) {
    asm volatile("ldmatrix.sync.aligned.m8n8.x2.shared.b16 {%0,%1}, [%2];"
        : "=r"(r0), "=r"(r1) : "r"(addr));
}
__device__ __forceinline__ void mma16(float* c, const uint32_t* a, const uint32_t* b) {
    asm volatile("mma.sync.aligned.m16n8k16.row.col.f32.bf16.bf16.f32 "
        "{%0,%1,%2,%3},{%4,%5,%6,%7},{%8,%9},{%0,%1,%2,%3};"
        : "+f"(c[0]), "+f"(c[1]), "+f"(c[2]), "+f"(c[3])
        : "r"(a[0]), "r"(a[1]), "r"(a[2]), "r"(a[3]), "r"(b[0]), "r"(b[1]));
}
__device__ __forceinline__ uint4 ldcg4(const void* p) {
    uint4 v;
    asm volatile("ld.global.cg.v4.u32 {%0,%1,%2,%3}, [%4];"
        : "=r"(v.x), "=r"(v.y), "=r"(v.z), "=r"(v.w) : "l"(p));
    return v;
}
__device__ __forceinline__ uint32_t swz(int row, int seg) {
    return (uint32_t)(row * 64 + (((seg + (row >> 1)) & 3) << 4));
}
__device__ __forceinline__ float sigf(float x) {
    return __fdividef(1.f, 1.f + __expf(-x));
}
__device__ __forceinline__ float tanhfast(float x) {
    float xc = fminf(fmaxf(x, -15.f), 15.f);
    float e = __expf(2.f * xc);
    return __fdividef(e - 1.f, e + 1.f);
}

// ---------------- mma chunk, warp tile 32x40, 80B-stride layout ----------------
__device__ __forceinline__ void mma_chunk80(uint32_t Ab, uint32_t Bb, int lane,
                                            int wm, int wn, float (&acc)[2][5][4]) {
    int r8 = lane & 7, sel = lane >> 3;
    int arow = ((sel & 1) << 3) + r8;
    int akoff = (sel >> 1) << 4;
    uint32_t ah[2][4], al[2][4];
#pragma unroll
    for (int im = 0; im < 2; im++) {
        uint32_t addr = Ab + (uint32_t)((wm + im * 16 + arow) * 80 + akoff);
        ldsm4(ah[im], addr);
        ldsm4(al[im], addr + 32);
    }
    uint32_t bh[5][2], bl[5][2];
    int brow = ((sel >> 1) << 3) + r8;
    int bkoff = (sel & 1) << 4;
#pragma unroll
    for (int j2 = 0; j2 < 2; j2++) {
        uint32_t addr = Bb + (uint32_t)((wn + j2 * 16 + brow) * 80 + bkoff);
        uint32_t t[4];
        ldsm4(t, addr);
        bh[2 * j2][0] = t[0]; bh[2 * j2][1] = t[1];
        bh[2 * j2 + 1][0] = t[2]; bh[2 * j2 + 1][1] = t[3];
        ldsm4(t, addr + 32);
        bl[2 * j2][0] = t[0]; bl[2 * j2][1] = t[1];
        bl[2 * j2 + 1][0] = t[2]; bl[2 * j2 + 1][1] = t[3];
    }
    {
        int row2 = lane & 7;
        int koff2 = ((lane >> 3) & 1) << 4;
        uint32_t addr = Bb + (uint32_t)((wn + 32 + row2) * 80 + koff2);
        ldsm2(bh[4][0], bh[4][1], addr);
        ldsm2(bl[4][0], bl[4][1], addr + 32);
    }
#pragma unroll
    for (int n8 = 0; n8 < 5; n8++)
#pragma unroll
        for (int im = 0; im < 2; im++) {
            mma16(acc[im][n8], ah[im], bh[n8]);
            mma16(acc[im][n8], al[im], bh[n8]);
            mma16(acc[im][n8], ah[im], bl[n8]);
        }
}

// ---------------- mma chunk, warp tile 32x40, swizzled 64B layout ----------------
__device__ __forceinline__ void mma_chunk64(uint32_t Ab, uint32_t Bb, int lane,
                                            int wm, int wn, float (&acc)[2][5][4]) {
    int r8 = lane & 7, sel = lane >> 3;
    int arow = ((sel & 1) << 3) + r8;
    int akseg = sel >> 1;
    uint32_t ah[2][4], al[2][4];
#pragma unroll
    for (int im = 0; im < 2; im++) {
        int row = wm + im * 16 + arow;
        ldsm4(ah[im], Ab + swz(row, akseg));
        ldsm4(al[im], Ab + swz(row, akseg + 2));
    }
    uint32_t bh[5][2], bl[5][2];
    int brow = ((sel >> 1) << 3) + r8;
    int bkseg = sel & 1;
#pragma unroll
    for (int j2 = 0; j2 < 2; j2++) {
        int row = wn + j2 * 16 + brow;
        uint32_t t[4];
        ldsm4(t, Bb + swz(row, bkseg));
        bh[2 * j2][0] = t[0]; bh[2 * j2][1] = t[1];
        bh[2 * j2 + 1][0] = t[2]; bh[2 * j2 + 1][1] = t[3];
        ldsm4(t, Bb + swz(row, bkseg + 2));
        bl[2 * j2][0] = t[0]; bl[2 * j2][1] = t[1];
        bl[2 * j2 + 1][0] = t[2]; bl[2 * j2 + 1][1] = t[3];
    }
    {
        int row = wn + 32 + (lane & 7);
        int seg = (lane >> 3) & 1;
        ldsm2(bh[4][0], bh[4][1], Bb + swz(row, seg));
        ldsm2(bl[4][0], bl[4][1], Bb + swz(row, seg + 2));
    }
#pragma unroll
    for (int n8 = 0; n8 < 5; n8++)
#pragma unroll
        for (int im = 0; im < 2; im++) {
            mma16(acc[im][n8], ah[im], bh[n8]);
            mma16(acc[im][n8], al[im], bh[n8]);
            mma16(acc[im][n8], ah[im], bl[n8]);
        }
}

// ---------------- init ----------------
__global__ void init_kernel() {
    int i = blockIdx.x * blockDim.x + threadIdx.x;
    if (i < 2 * 2 * B * KP) (&g_hpk[0][0][0])[i] = 0u;
    if (i < 16) (&g_cnt[0][0])[i] = 0;
}

__global__ void prep_whh(const float* __restrict__ Wf, const float* __restrict__ Wb) {
    int i = blockIdx.x * blockDim.x + threadIdx.x;
    if (i >= 2 * NPAD * KP) return;
    int dir = i / (NPAD * KP);
    int r = i - dir * (NPAD * KP);
    int np = r / KP, k = r - np * KP;
    float v = 0.f;
    if (np < G4 && k < H) {
        const float* W = dir ? Wb : Wf;
        v = W[(size_t)((np & 3) * H + (np >> 2)) * H + k];
    }
    float hi, lo; spb(v, hi, lo);
    g_Whi[dir][r] = __float2bfloat16(hi);
    g_Wlo[dir][r] = __float2bfloat16(lo);
}

__global__ void embed_kernel(const int* __restrict__ word,
                             const int* __restrict__ sem,
                             const float* __restrict__ wt,
                             const float* __restrict__ st) {
    int b = blockIdx.x;
    int e = threadIdx.x;
    __shared__ int sidx[L];
    __shared__ int widx;
    if (e < L) sidx[e] = sem[b * L + e];
    if (e == 0) widx = word[b];
    __syncthreads();
    if (e < E) {
        float acc = 0.f;
#pragma unroll
        for (int l = 0; l < L; l++) acc += st[sidx[l] * E + e];
        g_ag[b * E + e] = acc * (1.f / (float)L);
        g_w [b * E + e] = wt[widx * E + e];
    }
}

// ---------------- feed-forward gemm body (4-deep ring, sync per 2 chunks) ----------------
__device__ __forceinline__ void gemm_body(
    unsigned char* smraw,
    const float* A, int lda, const float* W, int ldw, int imap,
    const float* b1, const float* b2, float* C,
    int M, int N, int K, int dorelu, int bx, int by)
{
    uint32_t sbase = (uint32_t)__cvta_generic_to_shared(smraw);
    uint32_t* smw = (uint32_t*)smraw;

    int tid = threadIdx.x, lane = tid & 31, wid = tid >> 5;
    int g = lane >> 2, t4 = lane & 3;
    int wm = (wid >> 2) * 32, wn = (wid & 3) * 40;
    int m0 = by * 128, n0 = bx * 160;

    float acc[2][5][4];
#pragma unroll
    for (int a = 0; a < 2; a++)
#pragma unroll
        for (int b = 0; b < 5; b++)
#pragma unroll
            for (int c = 0; c < 4; c++) acc[a][b][c] = 0.f;

    int NC = (K + 15) / 16;
    int NG = (NC + 1) / 2;
    float4 ra[2], rb[2][2];

    auto loadregs = [&](int kc, int sl) {
        int k0 = kc * 16;
        {
            int row = tid >> 2, q4 = tid & 3;
            int gm = m0 + row, kk = k0 + q4 * 4;
            float4 v = make_float4(0.f, 0.f, 0.f, 0.f);
            if (gm < M) {
                const float* ap = A + (size_t)gm * lda;
                if (kk + 3 < K) v = *(const float4*)(ap + kk);
                else {
                    if (kk + 0 < K) v.x = ap[kk + 0];
                    if (kk + 1 < K) v.y = ap[kk + 1];
                    if (kk + 2 < K) v.z = ap[kk + 2];
                    if (kk + 3 < K) v.w = ap[kk + 3];
                }
            }
            ra[sl] = v;
        }
#pragma unroll
        for (int q = 0; q < 2; q++) {
            int p = tid + q * 512;
            float4 v = make_float4(0.f, 0.f, 0.f, 0.f);
            if (p < 640) {
                int row = p >> 2, q4 = p & 3;
                int nr = n0 + row, kk = k0 + q4 * 4;
                if (nr < N) {
                    int grow = imap ? ((nr & 3) * H + (nr >> 2)) : nr;
                    const float* wp = W + (size_t)grow * ldw;
                    if (kk + 3 < K) v = *(const float4*)(wp + kk);
                    else {
                        if (kk + 0 < K) v.x = wp[kk + 0];
                        if (kk + 1 < K) v.y = wp[kk + 1];
                        if (kk + 2 < K) v.z = wp[kk + 2];
                        if (kk + 3 < K) v.w = wp[kk + 3];
                    }
                }
            }
            rb[sl][q] = v;
        }
    };
    auto storeregs = [&](int sl, int buf) {
        uint32_t* Aw = smw + buf * (BUFB / 4);
        uint32_t* Bw = Aw + ABYTES / 4;
        {
            int row = tid >> 2, q4 = tid & 3;
            float h0, l0, h1, l1, h2, l2, h3, l3;
            spb(ra[sl].x, h0, l0); spb(ra[sl].y, h1, l1);
            spb(ra[sl].z, h2, l2); spb(ra[sl].w, h3, l3);
            Aw[row * 20 + q4 * 2]     = pack2(h0, h1);
            Aw[row * 20 + q4 * 2 + 1] = pack2(h2, h3);
            Aw[row * 20 + 8 + q4 * 2]     = pack2(l0, l1);
            Aw[row * 20 + 8 + q4 * 2 + 1] = pack2(l2, l3);
        }
#pragma unroll
        for (int q = 0; q < 2; q++) {
            int p = tid + q * 512;
            if (p < 640) {
                int row = p >> 2, q4 = p & 3;
                float h0, l0, h1, l1, h2, l2, h3, l3;
                spb(rb[sl][q].x, h0, l0); spb(rb[sl][q].y, h1, l1);
                spb(rb[sl][q].z, h2, l2); spb(rb[sl][q].w, h3, l3);
                Bw[row * 20 + q4 * 2]     = pack2(h0, h1);
                Bw[row * 20 + q4 * 2 + 1] = pack2(h2, h3);
                Bw[row * 20 + 8 + q4 * 2]     = pack2(l0, l1);
                Bw[row * 20 + 8 + q4 * 2 + 1] = pack2(l2, l3);
            }
        }
    };

    loadregs(0, 0);
    if (1 < NC) loadregs(1, 1);
    storeregs(0, 0);
    if (1 < NC) storeregs(1, 1);
    __syncthreads();
    for (int gg = 0; gg < NG; gg++) {
        int base2 = 2 * gg;
        if (gg + 1 < NG) {
            loadregs(base2 + 2, 0);
            if (base2 + 3 < NC) loadregs(base2 + 3, 1);
        }
        mma_chunk80(sbase + (uint32_t)((base2 & 3) * BUFB),
                    sbase + (uint32_t)((base2 & 3) * BUFB) + ABYTES, lane, wm, wn, acc);
        if (base2 + 1 < NC)
            mma_chunk80(sbase + (uint32_t)(((base2 + 1) & 3) * BUFB),
                        sbase + (uint32_t)(((base2 + 1) & 3) * BUFB) + ABYTES, lane, wm, wn, acc);
        if (gg + 1 < NG) {
            storeregs(0, (base2 + 2) & 3);
            if (base2 + 3 < NC) storeregs(1, (base2 + 3) & 3);
        }
        __syncthreads();
    }

#pragma unroll
    for (int in8 = 0; in8 < 5; in8++) {
        int n_g = n0 + wn + in8 * 8 + 2 * t4;
        float bv0 = 0.f, bv1 = 0.f;
        if (n_g < N) {
            int i0 = imap ? ((n_g & 3) * H + (n_g >> 2)) : n_g;
            if (b1) bv0 += b1[i0];
            if (b2) bv0 += b2[i0];
        }
        if (n_g + 1 < N) {
            int i1 = imap ? (((n_g + 1) & 3) * H + ((n_g + 1) >> 2)) : (n_g + 1);
            if (b1) bv1 += b1[i1];
            if (b2) bv1 += b2[i1];
        }
#pragma unroll
        for (int im = 0; im < 2; im++) {
            int r0 = m0 + wm + im * 16 + g;
            if (r0 < M) {
                if (n_g < N) {
                    float v = acc[im][in8][0] + bv0;
                    if (dorelu) v = fmaxf(v, 0.f);
                    C[(size_t)r0 * N + n_g] = v;
                }
                if (n_g + 1 < N) {
                    float v = acc[im][in8][1] + bv1;
                    if (dorelu) v = fmaxf(v, 0.f);
                    C[(size_t)r0 * N + n_g + 1] = v;
                }
            }
            int r1 = r0 + 8;
            if (r1 < M) {
                if (n_g < N) {
                    float v = acc[im][in8][2] + bv0;
                    if (dorelu) v = fmaxf(v, 0.f);
                    C[(size_t)r1 * N + n_g] = v;
                }
                if (n_g + 1 < N) {
                    float v = acc[im][in8][3] + bv1;
                    if (dorelu) v = fmaxf(v, 0.f);
                    C[(size_t)r1 * N + n_g + 1] = v;
                }
            }
        }
    }
}

// ---------------- merged feed-forward launch ----------------
__global__ void __launch_bounds__(512) gemm_ff(
    const float* Wb_, const float* bb_, const float* st,
    const float* Wih_f, const float* Wih_b,
    const float* bih_f, const float* bhh_f,
    const float* bih_b, const float* bhh_b,
    float* vg_out, float* psf, float* psb, float* pwf, float* pwb)
{
    extern __shared__ __align__(16) unsigned char smdyn[];
    int bid = blockIdx.x;
    if (bid < 16) {
        gemm_body(smdyn, g_ag, E, Wb_, E, 0, bb_, nullptr, vg_out,
                  B, E, E, 1, bid & 1, bid >> 1);
    } else if (bid < 160) {
        int r = bid - 16;
        gemm_body(smdyn, st, E, Wih_f + E, 2 * E, 1, bih_f, bhh_f, psf,
                  VS, G4, E, 0, r & 7, r >> 3);
    } else if (bid < 304) {
        int r = bid - 160;
        gemm_body(smdyn, st, E, Wih_b + E, 2 * E, 1, bih_b, bhh_b, psb,
                  VS, G4, E, 0, r & 7, r >> 3);
    } else if (bid < 368) {
        int r = bid - 304;
        gemm_body(smdyn, g_w, E, Wih_f, 2 * E, 1, nullptr, nullptr, pwf,
                  B, G4, E, 0, r & 7, r >> 3);
    } else {
        int r = bid - 368;
        gemm_body(smdyn, g_w, E, Wih_b, 2 * E, 1, nullptr, nullptr, pwb,
                  B, G4, E, 0, r & 7, r >> 3);
    }
}

__global__ void __launch_bounds__(512) gemm_v(
    const float* Wa, const float* ba, float* Vout)
{
    extern __shared__ __align__(16) unsigned char smdyn[];
    gemm_body(smdyn, g_Vh, 2 * H, Wa, 2 * H, 0, ba, nullptr, Vout,
              BL, H, 2 * H, 1, blockIdx.x, blockIdx.y);
}

// ---------------- persistent LSTM ----------------
__global__ void __launch_bounds__(512) lstm_persistent(const int* __restrict__ sem) {
    extern __shared__ __align__(16) unsigned char smraw[];
    uint32_t sbase = (uint32_t)__cvta_generic_to_shared(smraw);
    const int dir = blockIdx.z, mt = blockIdx.y, nt = blockIdx.x;
    const int m0 = mt * 128, n0 = nt * 160;

    int tid = threadIdx.x, lane = tid & 31, wid = tid >> 5;
    int g = lane >> 2, t4 = lane & 3;
    int wm = (wid >> 2) * 32, wn = (wid & 3) * 40;
    int parity = lane & 1;

    uint32_t Abase = sbase;           // 4 buffers x 8192
    uint32_t Bbase = sbase + 32768;   // 19 chunks x 10240

    // load Whh tile into smem once (swizzled)
    {
        const __nv_bfloat16* Whi = g_Whi[dir];
        const __nv_bfloat16* Wlo = g_Wlo[dir];
        for (int p = tid; p < 19 * 640; p += 512) {
            int kc = p / 640, r = p - kc * 640;
            int row = r >> 2, seg = r & 3;
            int plane = seg >> 1, half = seg & 1;
            const __nv_bfloat16* src = plane ? Wlo : Whi;
            uint4 v = *(const uint4*)(src + (size_t)(n0 + row) * KP + kc * 16 + half * 8);
            *(uint4*)(smraw + 32768 + kc * 10240 + swz(row, seg)) = v;
        }
    }
    __syncthreads();

    const float* sproj = g_sproj[dir];
    const float* wproj = g_wproj[dir];

    float cst[2][5];
#pragma unroll
    for (int a = 0; a < 2; a++)
#pragma unroll
        for (int b = 0; b < 5; b++) cst[a][b] = 0.f;

    for (int s = 0; s < L; s++) {
        float acc[2][5][4];
#pragma unroll
        for (int a = 0; a < 2; a++)
#pragma unroll
            for (int b = 0; b < 5; b++)
#pragma unroll
                for (int c = 0; c < 4; c++) acc[a][b][c] = 0.f;

        if (s > 0) {
            const uint32_t* Apk = g_hpk[dir][(s - 1) & 1];
            uint4 ua[2];
            int arow = tid >> 2, akq = tid & 3;
            auto loadA = [&](int kc, int sl) {
                ua[sl] = ldcg4(Apk + (size_t)(m0 + arow) * KP + kc * 16 + akq * 4);
            };
            auto storeA = [&](int sl, int buf) {
                uint4 u = ua[sl];
                uint32_t hiA = __byte_perm(u.x, u.y, 0x5410);
                uint32_t hiB = __byte_perm(u.z, u.w, 0x5410);
                uint32_t loA = __byte_perm(u.x, u.y, 0x7632);
                uint32_t loB = __byte_perm(u.z, u.w, 0x7632);
                uint32_t base = (uint32_t)(buf * 8192);
                *(uint2*)(smraw + base + swz(arow, akq >> 1) + (akq & 1) * 8)
                    = make_uint2(hiA, hiB);
                *(uint2*)(smraw + base + swz(arow, (akq >> 1) + 2) + (akq & 1) * 8)
                    = make_uint2(loA, loB);
            };
            const int NC = 19, NG = 10;
            loadA(0, 0); loadA(1, 1);
            storeA(0, 0); storeA(1, 1);
            __syncthreads();
            for (int gg = 0; gg < NG; gg++) {
                int base2 = 2 * gg;
                if (gg + 1 < NG) {
                    loadA(base2 + 2, 0);
                    if (base2 + 3 < NC) loadA(base2 + 3, 1);
                }
                mma_chunk64(Abase + (uint32_t)((base2 & 3) * 8192),
                            Bbase + (uint32_t)(base2 * 10240), lane, wm, wn, acc);
                if (base2 + 1 < NC)
                    mma_chunk64(Abase + (uint32_t)(((base2 + 1) & 3) * 8192),
                                Bbase + (uint32_t)((base2 + 1) * 10240), lane, wm, wn, acc);
                if (gg + 1 < NG) {
                    storeA(0, (base2 + 2) & 3);
                    if (base2 + 3 < NC) storeA(1, (base2 + 3) & 3);
                }
                __syncthreads();
            }
        }

        // epilogue
        int t = dir ? (L - 1 - s) : s;
        uint32_t* Hpk = g_hpk[dir][s & 1];
#pragma unroll
        for (int im = 0; im < 2; im++) {
            int rowl = wm + im * 16 + g + (parity ? 8 : 0);
            int b = m0 + rowl;
            int idx = sem[b * L + t];
            const float* sp = sproj + (size_t)idx * G4;
            const float* wp = wproj + (size_t)b * G4;
            float wmul = (idx != 0) ? 1.f : 0.f;
#pragma unroll
            for (int n8 = 0; n8 < 5; n8++) {
                float c0 = acc[im][n8][0], c1 = acc[im][n8][1];
                float c2 = acc[im][n8][2], c3 = acc[im][n8][3];
                float s1 = parity ? c0 : c2;
                float s2 = parity ? c1 : c3;
                float r1 = __shfl_xor_sync(0xffffffffu, s1, 1);
                float r2 = __shfl_xor_sync(0xffffffffu, s2, 1);
                float gi, gf, gg, go;
                if (!parity) { gi = c0; gf = c1; gg = r1; go = r2; }
                else         { gi = r1; gf = r2; gg = c2; go = c3; }
                int j = (n0 + wn + n8 * 8 + 2 * t4) >> 2;
                if (j < H) {
                    float4 spv = *(const float4*)(sp + 4 * j);
                    float4 wpv = *(const float4*)(wp + 4 * j);
                    gi += spv.x + wmul * wpv.x;
                    gf += spv.y + wmul * wpv.y;
                    gg += spv.z + wmul * wpv.z;
                    go += spv.w + wmul * wpv.w;
                    float ig = sigf(gi);
                    float fg = sigf(gf);
                    float gt = tanhfast(gg);
                    float og = sigf(go);
                    float cn = fg * cst[im][n8] + ig * gt;
                    cst[im][n8] = cn;
                    float h = og * tanhfast(cn);
                    g_Vh[(size_t)(b * L + t) * (2 * H) + dir * H + j] = h;
                    float hh, hl; spb(h, hh, hl);
                    Hpk[(size_t)b * KP + j] = pack2(hh, hl);
                }
            }
        }

        // group barrier: release/acquire, no full membar
        if (s < L - 1) {
            __syncthreads();
            if (tid == 0) {
                int* cp = &g_cnt[dir][mt];
                asm volatile("red.release.gpu.global.add.s32 [%0], 1;"
                             :: "l"(cp) : "memory");
                int target = 8 * (s + 1);
                int v;
                while (true) {
                    asm volatile("ld.acquire.gpu.global.b32 %0, [%1];"
                                 : "=r"(v) : "l"(cp) : "memory");
                    if (v >= target) break;
                    __nanosleep(64);
                }
            }
            __syncthreads();
        }
    }
}

// ---------------- launch ----------------
extern "C" void kernel_launch(void* const* d_in, const int* in_sizes, int n_in,
                              void* d_out, int out_size) {
    const int*   word  = (const int*)d_in[0];
    const int*   sem   = (const int*)d_in[1];
    const float* wt    = (const float*)d_in[2];
    const float* st    = (const float*)d_in[3];
    const float* Wih_f = (const float*)d_in[4];
    const float* Whh_f = (const float*)d_in[5];
    const float* bih_f = (const float*)d_in[6];
    const float* bhh_f = (const float*)d_in[7];
    const float* Wih_b = (const float*)d_in[8];
    const float* Whh_b = (const float*)d_in[9];
    const float* bih_b = (const float*)d_in[10];
    const float* bhh_b = (const float*)d_in[11];
    const float* Wa    = (const float*)d_in[12];
    const float* ba    = (const float*)d_in[13];
    const float* Wb    = (const float*)d_in[14];
    const float* bb    = (const float*)d_in[15];

    float* out    = (float*)d_out;
    float* Vout   = out;
    float* vg_out = out + (size_t)B * L * H;

    void* p;
    float *psf, *psb, *pwf, *pwb;
    cudaGetSymbolAddress(&p, g_sproj); psf = (float*)p; psb = psf + (size_t)VS * G4;
    cudaGetSymbolAddress(&p, g_wproj); pwf = (float*)p; pwb = pwf + (size_t)B * G4;

    cudaFuncSetAttribute(lstm_persistent,
                         cudaFuncAttributeMaxDynamicSharedMemorySize, PSMEM);
    cudaFuncSetAttribute(gemm_ff,
                         cudaFuncAttributeMaxDynamicSharedMemorySize, FFSMEM);
    cudaFuncSetAttribute(gemm_v,
                         cudaFuncAttributeMaxDynamicSharedMemorySize, FFSMEM);

    init_kernel<<<(2 * 2 * B * KP + 255) / 256, 256>>>();
    prep_whh<<<(2 * NPAD * KP + 255) / 256, 256>>>(Whh_f, Whh_b);
    embed_kernel<<<B, 320>>>(word, sem, wt, st);

    gemm_ff<<<432, 512, FFSMEM>>>(Wb, bb, st, Wih_f, Wih_b,
                                  bih_f, bhh_f, bih_b, bhh_b,
                                  vg_out, psf, psb, pwf, pwb);

    lstm_persistent<<<dim3(8, 8, 2), 512, PSMEM>>>(sem);

    gemm_v<<<dim3(2, 144), 512, FFSMEM>>>(Wa, ba, Vout);
}